// round 6
// baseline (speedup 1.0000x reference)
#include <cuda_runtime.h>
#include <cstdint>

#define NN 100000
#define EE 1600000
#define FIN 128
#define HID 64
#define NG 512
#define BN_EPS_F 1e-5f

#define SCAN_CHUNK 1024
#define NCHUNK ((NN + SCAN_CHUNK - 1) / SCAN_CHUNK)   // 98

// GEMM tiling: block = 128 threads, tile 128(m) x 64(n), micro-tile 8x8
#define MT 128
#define NT 64
#define KC 64
#define ASTR 132           // As row stride (floats); 132*4B % 16 == 0
#define WSTR 72            // Ws row stride (floats); cols get +4 shift for n>=32

// Scratch (allocation-free rule: __device__ globals).
__device__ __align__(16) float g_Y[(size_t)NN * HID];
__device__ __align__(16) float g_A[(size_t)NN * HID];
__device__ int g_cnt[NN];
__device__ int g_scan[NN];
__device__ int g_bsum[NCHUNK];
__device__ int g_rowptr[NN + 1];
__device__ int g_cursor[NN];
__device__ int g_ss[EE];

__device__ __forceinline__ void red_add_v4(float* p, float a, float b, float c, float d) {
    asm volatile("red.global.add.v4.f32 [%0], {%1,%2,%3,%4};"
                 :: "l"(p), "f"(a), "f"(b), "f"(c), "f"(d) : "memory");
}

// ---------------------------------------------------------------- fused zero
__global__ void k_zero_all(float* __restrict__ out) {
    int i = blockIdx.x * blockDim.x + threadIdx.x;
    if (i < NG * HID) out[i] = 0.f;
    if (i < NN) g_cnt[i] = 0;
}

// ---------------------------------------------------------------- CSR build
__global__ void k_hist(const int* __restrict__ ei) {
    int e = blockIdx.x * blockDim.x + threadIdx.x;
    if (e < EE) atomicAdd(&g_cnt[ei[EE + e]], 1);
}

__global__ __launch_bounds__(SCAN_CHUNK) void k_scan1() {
    __shared__ int s[SCAN_CHUNK];
    int tid = threadIdx.x;
    int i = blockIdx.x * SCAN_CHUNK + tid;
    int v = (i < NN) ? g_cnt[i] : 0;
    s[tid] = v;
    __syncthreads();
#pragma unroll
    for (int off = 1; off < SCAN_CHUNK; off <<= 1) {
        int t = (tid >= off) ? s[tid - off] : 0;
        __syncthreads();
        s[tid] += t;
        __syncthreads();
    }
    if (i < NN) g_scan[i] = s[tid];
    if (tid == SCAN_CHUNK - 1) g_bsum[blockIdx.x] = s[tid];
}

__global__ void k_scan3f() {
    __shared__ int boff[NCHUNK];
    if (threadIdx.x == 0) {
        int run = 0;
#pragma unroll 2
        for (int c = 0; c < NCHUNK; c++) { int t = g_bsum[c]; boff[c] = run; run += t; }
    }
    __syncthreads();
    int i = blockIdx.x * blockDim.x + threadIdx.x;
    if (i >= NN) return;
    int incl = g_scan[i] + boff[i / SCAN_CHUNK];
    g_rowptr[i + 1] = incl;
    g_cursor[i] = incl - g_cnt[i];
    if (i == 0) g_rowptr[0] = 0;
}

__global__ void k_reorder(const int* __restrict__ ei) {
    int e = blockIdx.x * blockDim.x + threadIdx.x;
    if (e >= EE) return;
    int d = ei[EE + e];
    int pos = atomicAdd(&g_cursor[d], 1);
    g_ss[pos] = ei[e];
}

// ---------------------------------------------------------------- aggregation
__global__ __launch_bounds__(256) void k_agg(const float* __restrict__ b) {
    int t = blockIdx.x * 256 + threadIdx.x;
    int n = t >> 4;
    int lane = t & 15;
    if (n >= NN) return;

    const float4* Y4 = (const float4*)g_Y;
    float4 bv = ((const float4*)b)[lane];
    float4 acc = Y4[(size_t)n * 16 + lane];
    acc.x += bv.x; acc.y += bv.y; acc.z += bv.z; acc.w += bv.w;

    int beg = g_rowptr[n], end = g_rowptr[n + 1];
#pragma unroll 4
    for (int e = beg; e < end; e++) {
        int s = g_ss[e];
        float4 v = Y4[(size_t)s * 16 + lane];
        acc.x += v.x; acc.y += v.y; acc.z += v.z; acc.w += v.w;
    }
    ((float4*)g_A)[(size_t)n * 16 + lane] = acc;
}

// ---------------------------------------------------------------- micro-kernel helpers
__device__ __forceinline__ void mk_fma(float acc[8][8], const float* As, const float* wb,
                                       int k, int tm, int woff)
{
    float4 a01 = *(const float4*)(As + k * ASTR + tm * 8);
    float4 a23 = *(const float4*)(As + k * ASTR + tm * 8 + 4);
    float4 w01 = *(const float4*)(wb + k * WSTR + woff);
    float4 w23 = *(const float4*)(wb + k * WSTR + woff + 4);
    float av[8] = {a01.x, a01.y, a01.z, a01.w, a23.x, a23.y, a23.z, a23.w};
    float wv[8] = {w01.x, w01.y, w01.z, w01.w, w23.x, w23.y, w23.z, w23.w};
#pragma unroll
    for (int r = 0; r < 8; r++)
#pragma unroll
        for (int c = 0; c < 8; c++)
            acc[r][c] = fmaf(av[r], wv[c], acc[r][c]);
}

// ---------------------------------------------------------------- tiled GEMM (in_proj / final)
// EPI 0: plain write to Yout. EPI 2: bn+relu then pool-RED into out[batch[n]].
template<int K, bool RELU_IN, int EPI>
__global__ __launch_bounds__(128) void k_gemm(
    const float* __restrict__ Asrc, const float* __restrict__ W,
    float* __restrict__ Yout,
    const float* __restrict__ bb, const float* __restrict__ ga,
    const float* __restrict__ be, const float* __restrict__ mm,
    const float* __restrict__ vv,
    const int* __restrict__ batch, float* __restrict__ out)
{
    extern __shared__ float sm[];
    float* Ws = sm;                         // [K][WSTR] padded
    float* As = Ws + K * WSTR;              // [KC][ASTR]
    float* sc = As + KC * ASTR;
    float* sh = sc + NT;

    int tid = threadIdx.x;
    // W stage: lanes span n (consecutive) -> conflict-free STS; gmem L1-cached
    for (int i = tid; i < K * NT; i += 128) {
        int k = i >> 6, n = i & 63;
        Ws[k * WSTR + n + ((n >> 5) << 2)] = W[n * K + k];
    }
    if (EPI == 2 && tid < NT) {
        float s = ga[tid] * rsqrtf(vv[tid] + BN_EPS_F);
        sc[tid] = s;
        sh[tid] = (bb[tid] - mm[tid]) * s + be[tid];
    }

    int m0 = blockIdx.x * MT;
    int tm = tid >> 3, tn = tid & 7;
    int woff = tn * 8 + ((tn >> 2) << 2);

    int gmrow = m0 + tid;
    bool rowOK = gmrow < NN;
    const float4* arow = (const float4*)(Asrc + (size_t)gmrow * K);

    float acc[8][8];
#pragma unroll
    for (int r = 0; r < 8; r++)
#pragma unroll
        for (int c = 0; c < 8; c++) acc[r][c] = 0.f;

#pragma unroll
    for (int kc = 0; kc < K / KC; kc++) {
        __syncthreads();
        // A stage: lane = row m -> transpose STS conflict-free
#pragma unroll
        for (int it = 0; it < KC / 4; it++) {
            float4 v = rowOK ? arow[kc * (KC / 4) + it] : make_float4(0.f, 0.f, 0.f, 0.f);
            if (RELU_IN) {
                v.x = fmaxf(v.x, 0.f); v.y = fmaxf(v.y, 0.f);
                v.z = fmaxf(v.z, 0.f); v.w = fmaxf(v.w, 0.f);
            }
            As[(4 * it + 0) * ASTR + tid] = v.x;
            As[(4 * it + 1) * ASTR + tid] = v.y;
            As[(4 * it + 2) * ASTR + tid] = v.z;
            As[(4 * it + 3) * ASTR + tid] = v.w;
        }
        __syncthreads();

        const float* wb = Ws + kc * KC * WSTR;
#pragma unroll 4
        for (int k = 0; k < KC; k++)
            mk_fma(acc, As, wb, k, tm, woff);
    }

    if (EPI == 0) {
#pragma unroll
        for (int r = 0; r < 8; r++) {
            int gm = m0 + tm * 8 + r;
            if (gm < NN) {
                *(float4*)(Yout + (size_t)gm * NT + tn * 8) =
                    make_float4(acc[r][0], acc[r][1], acc[r][2], acc[r][3]);
                *(float4*)(Yout + (size_t)gm * NT + tn * 8 + 4) =
                    make_float4(acc[r][4], acc[r][5], acc[r][6], acc[r][7]);
            }
        }
    } else {
        float4 s0 = *(const float4*)(sc + tn * 8);
        float4 s1 = *(const float4*)(sc + tn * 8 + 4);
        float4 t0 = *(const float4*)(sh + tn * 8);
        float4 t1 = *(const float4*)(sh + tn * 8 + 4);
#pragma unroll
        for (int r = 0; r < 8; r++) {
            int gm = m0 + tm * 8 + r;
            if (gm >= NN) continue;
            float h0 = fmaxf(fmaf(acc[r][0], s0.x, t0.x), 0.f);
            float h1 = fmaxf(fmaf(acc[r][1], s0.y, t0.y), 0.f);
            float h2 = fmaxf(fmaf(acc[r][2], s0.z, t0.z), 0.f);
            float h3 = fmaxf(fmaf(acc[r][3], s0.w, t0.w), 0.f);
            float h4 = fmaxf(fmaf(acc[r][4], s1.x, t1.x), 0.f);
            float h5 = fmaxf(fmaf(acc[r][5], s1.y, t1.y), 0.f);
            float h6 = fmaxf(fmaf(acc[r][6], s1.z, t1.z), 0.f);
            float h7 = fmaxf(fmaf(acc[r][7], s1.w, t1.w), 0.f);
            int g = batch[gm];
            red_add_v4(out + (size_t)g * NT + tn * 8, h0, h1, h2, h3);
            red_add_v4(out + (size_t)g * NT + tn * 8 + 4, h4, h5, h6, h7);
        }
    }
}

// ---------------------------------------------------------------- k_mid: fused
//   H = relu(bn1(relu(A1) @ W1b^T + b1b));  Y2 = H @ W2a^T -> g_Y
__global__ __launch_bounds__(128) void k_mid(
    const float* __restrict__ W1b, const float* __restrict__ b1b,
    const float* __restrict__ g1,  const float* __restrict__ be1,
    const float* __restrict__ m1,  const float* __restrict__ v1,
    const float* __restrict__ W2a)
{
    extern __shared__ float sm[];
    float* Ws1 = sm;                        // [64][WSTR]
    float* Ws2 = Ws1 + HID * WSTR;          // [64][WSTR]
    float* As  = Ws2 + HID * WSTR;          // [KC][ASTR]
    float* sc  = As + KC * ASTR;
    float* sh  = sc + NT;

    int tid = threadIdx.x;
    for (int i = tid; i < HID * NT; i += 128) {
        int k = i >> 6, n = i & 63;
        int nc = n + ((n >> 5) << 2);
        Ws1[k * WSTR + nc] = W1b[n * HID + k];
        Ws2[k * WSTR + nc] = W2a[n * HID + k];
    }
    if (tid < NT) {
        float s = g1[tid] * rsqrtf(v1[tid] + BN_EPS_F);
        sc[tid] = s;
        sh[tid] = (b1b[tid] - m1[tid]) * s + be1[tid];
    }

    int m0 = blockIdx.x * MT;
    int tm = tid >> 3, tn = tid & 7;
    int woff = tn * 8 + ((tn >> 2) << 2);

    int gmrow = m0 + tid;
    bool rowOK = gmrow < NN;
    const float4* arow = (const float4*)(g_A + (size_t)gmrow * HID);

    __syncthreads();
    // stage relu(A1) transposed, lane = row
#pragma unroll
    for (int it = 0; it < KC / 4; it++) {
        float4 v = rowOK ? arow[it] : make_float4(0.f, 0.f, 0.f, 0.f);
        v.x = fmaxf(v.x, 0.f); v.y = fmaxf(v.y, 0.f);
        v.z = fmaxf(v.z, 0.f); v.w = fmaxf(v.w, 0.f);
        As[(4 * it + 0) * ASTR + tid] = v.x;
        As[(4 * it + 1) * ASTR + tid] = v.y;
        As[(4 * it + 2) * ASTR + tid] = v.z;
        As[(4 * it + 3) * ASTR + tid] = v.w;
    }
    __syncthreads();

    float acc[8][8];
#pragma unroll
    for (int r = 0; r < 8; r++)
#pragma unroll
        for (int c = 0; c < 8; c++) acc[r][c] = 0.f;

    // phase 1
#pragma unroll 4
    for (int k = 0; k < KC; k++)
        mk_fma(acc, As, Ws1, k, tm, woff);
    __syncthreads();

    // bn1+relu, write H back into As as [n][m]; float4 along m (acc rows)
#pragma unroll
    for (int c = 0; c < 8; c++) {
        int n = tn * 8 + c;
        float s = sc[n], t = sh[n];
        float4 v0 = make_float4(fmaxf(fmaf(acc[0][c], s, t), 0.f),
                                fmaxf(fmaf(acc[1][c], s, t), 0.f),
                                fmaxf(fmaf(acc[2][c], s, t), 0.f),
                                fmaxf(fmaf(acc[3][c], s, t), 0.f));
        float4 v1 = make_float4(fmaxf(fmaf(acc[4][c], s, t), 0.f),
                                fmaxf(fmaf(acc[5][c], s, t), 0.f),
                                fmaxf(fmaf(acc[6][c], s, t), 0.f),
                                fmaxf(fmaf(acc[7][c], s, t), 0.f));
        *(float4*)(As + n * ASTR + tm * 8) = v0;
        *(float4*)(As + n * ASTR + tm * 8 + 4) = v1;
    }
    __syncthreads();

    // phase 2
#pragma unroll
    for (int r = 0; r < 8; r++)
#pragma unroll
        for (int c = 0; c < 8; c++) acc[r][c] = 0.f;

#pragma unroll 4
    for (int k = 0; k < KC; k++)
        mk_fma(acc, As, Ws2, k, tm, woff);

#pragma unroll
    for (int r = 0; r < 8; r++) {
        int gm = m0 + tm * 8 + r;
        if (gm < NN) {
            *(float4*)(g_Y + (size_t)gm * HID + tn * 8) =
                make_float4(acc[r][0], acc[r][1], acc[r][2], acc[r][3]);
            *(float4*)(g_Y + (size_t)gm * HID + tn * 8 + 4) =
                make_float4(acc[r][4], acc[r][5], acc[r][6], acc[r][7]);
        }
    }
}

// ------------------------------------------------- divide by per-graph counts
__global__ void k_div(const int* __restrict__ batch, float* __restrict__ out)
{
    int g = blockIdx.x;
    __shared__ int cnt;
    if (threadIdx.x == 0) {
        int lo = 0, hi = NN;
        while (lo < hi) { int mid = (lo + hi) >> 1; if (batch[mid] < g) lo = mid + 1; else hi = mid; }
        int lo2 = lo, hi2 = NN;
        while (lo2 < hi2) { int mid = (lo2 + hi2) >> 1; if (batch[mid] < g + 1) lo2 = mid + 1; else hi2 = mid; }
        cnt = lo2 - lo;
    }
    __syncthreads();
    float c = (float)(cnt > 1 ? cnt : 1);
    out[(size_t)g * HID + threadIdx.x] /= c;
}

// ---------------------------------------------------------------- launch
extern "C" void kernel_launch(void* const* d_in, const int* in_sizes, int n_in,
                              void* d_out, int out_size)
{
    (void)in_sizes; (void)n_in; (void)out_size;
    const float* x    = (const float*)d_in[0];
    const int*   ei   = (const int*)d_in[1];
    const int*   batch= (const int*)d_in[2];
    const float* W1a  = (const float*)d_in[3];
    const float* b1a  = (const float*)d_in[4];
    const float* W1b  = (const float*)d_in[5];
    const float* b1b  = (const float*)d_in[6];
    const float* g1   = (const float*)d_in[7];
    const float* be1  = (const float*)d_in[8];
    const float* m1   = (const float*)d_in[9];
    const float* v1   = (const float*)d_in[10];
    const float* W2a  = (const float*)d_in[11];
    const float* b2a  = (const float*)d_in[12];
    const float* W2b  = (const float*)d_in[13];
    const float* b2b  = (const float*)d_in[14];
    const float* g2   = (const float*)d_in[15];
    const float* be2  = (const float*)d_in[16];
    const float* m2   = (const float*)d_in[17];
    const float* v2   = (const float*)d_in[18];
    float* out = (float*)d_out;

    float* yP;  cudaGetSymbolAddress((void**)&yP, g_Y);
    float* aP;  cudaGetSymbolAddress((void**)&aP, g_A);

    const int smem64  = (HID * WSTR + KC * ASTR + 2 * NT) * (int)sizeof(float);      // ~52.7KB
    const int smem128 = (FIN * WSTR + KC * ASTR + 2 * NT) * (int)sizeof(float);      // ~71.2KB
    const int smemMid = (2 * HID * WSTR + KC * ASTR + 2 * NT) * (int)sizeof(float);  // ~71.2KB
    cudaFuncSetAttribute(k_gemm<FIN, false, 0>, cudaFuncAttributeMaxDynamicSharedMemorySize, smem128);
    cudaFuncSetAttribute(k_mid,                 cudaFuncAttributeMaxDynamicSharedMemorySize, smemMid);
    cudaFuncSetAttribute(k_gemm<HID, true, 2>,  cudaFuncAttributeMaxDynamicSharedMemorySize, smem64);

    int gemmBlocks = (NN + MT - 1) / MT;           // 782
    int edgeBlocks = (EE + 255) / 256;             // 6250
    int aggBlocks  = (NN * 16 + 255) / 256;        // 6250

    k_zero_all<<<(NN + 255) / 256, 256>>>(out);
    k_hist<<<edgeBlocks, 256>>>(ei);
    k_scan1<<<NCHUNK, SCAN_CHUNK>>>();
    // slot 4 (profiled): K=128 GEMM — dependency-free w.r.t. CSR chain
    k_gemm<FIN, false, 0><<<gemmBlocks, 128, smem128>>>(
        x, W1a, yP, nullptr, nullptr, nullptr, nullptr, nullptr, nullptr, nullptr);
    k_scan3f<<<(NN + 255) / 256, 256>>>();
    k_reorder<<<edgeBlocks, 256>>>(ei);

    // layer 1 + mid
    k_agg<<<aggBlocks, 256>>>(b1a);
    k_mid<<<gemmBlocks, 128, smemMid>>>(W1b, b1b, g1, be1, m1, v1, W2a);

    // layer 2
    k_agg<<<aggBlocks, 256>>>(b2a);
    k_gemm<HID, true, 2><<<gemmBlocks, 128, smem64>>>(
        aP, W2b, nullptr, b2b, g2, be2, m2, v2, batch, out);
    k_div<<<NG, HID>>>(batch, out);
}

// round 7
// speedup vs baseline: 1.0719x; 1.0719x over previous
#include <cuda_runtime.h>
#include <cstdint>

#define NN 100000
#define EE 1600000
#define FIN 128
#define HID 64
#define NG 512
#define BN_EPS_F 1e-5f

#define SCAN_CHUNK 1024
#define NCHUNK ((NN + SCAN_CHUNK - 1) / SCAN_CHUNK)   // 98

// GEMM tiling: block = 256 threads, tile 128(m) x 64(n), micro-tile 8x4
#define MT 128
#define NT 64
#define KC 64
#define ASTR 132           // As row stride (floats); 132*4 % 16 == 0

typedef unsigned long long ull;

// Scratch (allocation-free rule: __device__ globals).
__device__ __align__(16) float g_Y[(size_t)NN * HID];
__device__ __align__(16) float g_A[(size_t)NN * HID];
__device__ int g_cnt[NN];
__device__ int g_scan[NN];
__device__ int g_bsum[NCHUNK];
__device__ int g_rowptr[NN + 1];
__device__ int g_cursor[NN];
__device__ int g_ss[EE];

__device__ __forceinline__ void red_add_v4(float* p, float a, float b, float c, float d) {
    asm volatile("red.global.add.v4.f32 [%0], {%1,%2,%3,%4};"
                 :: "l"(p), "f"(a), "f"(b), "f"(c), "f"(d) : "memory");
}

// ---- packed f32x2 helpers (Blackwell FFMA2; ptxas never emits this from C++)
__device__ __forceinline__ ull splat2(float x) {
    ull r; asm("mov.b64 %0, {%1, %1};" : "=l"(r) : "f"(x)); return r;
}
__device__ __forceinline__ void fma2(ull& d, ull a, ull b) {
    asm("fma.rn.f32x2 %0, %1, %2, %0;" : "+l"(d) : "l"(a), "l"(b));
}
__device__ __forceinline__ float2 unpk(ull v) {
    float2 f; asm("mov.b64 {%0, %1}, %2;" : "=f"(f.x), "=f"(f.y) : "l"(v)); return f;
}

// ---------------------------------------------------------------- fused zero
__global__ void k_zero_all(float* __restrict__ out) {
    int i = blockIdx.x * blockDim.x + threadIdx.x;
    if (i < NG * HID) out[i] = 0.f;
    if (i < NN) g_cnt[i] = 0;
}

// ---------------------------------------------------------------- CSR build
__global__ void k_hist(const int* __restrict__ ei) {
    int e = blockIdx.x * blockDim.x + threadIdx.x;
    if (e < EE) atomicAdd(&g_cnt[ei[EE + e]], 1);
}

__global__ __launch_bounds__(SCAN_CHUNK) void k_scan1() {
    __shared__ int s[SCAN_CHUNK];
    int tid = threadIdx.x;
    int i = blockIdx.x * SCAN_CHUNK + tid;
    int v = (i < NN) ? g_cnt[i] : 0;
    s[tid] = v;
    __syncthreads();
#pragma unroll
    for (int off = 1; off < SCAN_CHUNK; off <<= 1) {
        int t = (tid >= off) ? s[tid - off] : 0;
        __syncthreads();
        s[tid] += t;
        __syncthreads();
    }
    if (i < NN) g_scan[i] = s[tid];
    if (tid == SCAN_CHUNK - 1) g_bsum[blockIdx.x] = s[tid];
}

__global__ void k_scan3f() {
    __shared__ int boff[NCHUNK];
    if (threadIdx.x == 0) {
        int run = 0;
#pragma unroll 2
        for (int c = 0; c < NCHUNK; c++) { int t = g_bsum[c]; boff[c] = run; run += t; }
    }
    __syncthreads();
    int i = blockIdx.x * blockDim.x + threadIdx.x;
    if (i >= NN) return;
    int incl = g_scan[i] + boff[i / SCAN_CHUNK];
    g_rowptr[i + 1] = incl;
    g_cursor[i] = incl - g_cnt[i];
    if (i == 0) g_rowptr[0] = 0;
}

__global__ void k_reorder(const int* __restrict__ ei) {
    int e = blockIdx.x * blockDim.x + threadIdx.x;
    if (e >= EE) return;
    int d = ei[EE + e];
    int pos = atomicAdd(&g_cursor[d], 1);
    g_ss[pos] = ei[e];
}

// ---------------------------------------------------------------- aggregation
__global__ __launch_bounds__(256) void k_agg(const float* __restrict__ b) {
    int t = blockIdx.x * 256 + threadIdx.x;
    int n = t >> 4;
    int lane = t & 15;
    if (n >= NN) return;

    const float4* Y4 = (const float4*)g_Y;
    float4 bv = ((const float4*)b)[lane];
    float4 acc = Y4[(size_t)n * 16 + lane];
    acc.x += bv.x; acc.y += bv.y; acc.z += bv.z; acc.w += bv.w;

    int beg = g_rowptr[n], end = g_rowptr[n + 1];
#pragma unroll 4
    for (int e = beg; e < end; e++) {
        int s = g_ss[e];
        float4 v = Y4[(size_t)s * 16 + lane];
        acc.x += v.x; acc.y += v.y; acc.z += v.z; acc.w += v.w;
    }
    ((float4*)g_A)[(size_t)n * 16 + lane] = acc;
}

// ---------------------------------------------------------------- f32x2 micro-kernel
// acc[rp][c]: row-pair rp packs rows (2rp, 2rp+1) of the 8-row micro-tile, col c.
__device__ __forceinline__ void mk_fma2(ull acc[4][4], const float* As, const float* wb,
                                        int k, int tm, int tn)
{
    ulonglong2 a01 = *(const ulonglong2*)(As + k * ASTR + tm * 8);
    ulonglong2 a23 = *(const ulonglong2*)(As + k * ASTR + tm * 8 + 4);
    float4 w = *(const float4*)(wb + k * NT + tn * 4);
    ull av[4] = {a01.x, a01.y, a23.x, a23.y};
    ull wv[4] = {splat2(w.x), splat2(w.y), splat2(w.z), splat2(w.w)};
#pragma unroll
    for (int rp = 0; rp < 4; rp++)
#pragma unroll
        for (int c = 0; c < 4; c++)
            fma2(acc[rp][c], av[rp], wv[c]);
}

// ---------------------------------------------------------------- tiled GEMM (in_proj / final)
// EPI 0: plain write to Yout. EPI 2: bn+relu then pool-RED into out[batch[n]].
template<int K, bool RELU_IN, int EPI>
__global__ __launch_bounds__(256, 3) void k_gemm(
    const float* __restrict__ Asrc, const float* __restrict__ W,
    float* __restrict__ Yout,
    const float* __restrict__ bb, const float* __restrict__ ga,
    const float* __restrict__ be, const float* __restrict__ mm,
    const float* __restrict__ vv,
    const int* __restrict__ batch, float* __restrict__ out)
{
    extern __shared__ float sm[];
    float* Ws = sm;                         // [K][NT]
    float* As = Ws + K * NT;                // [KC][ASTR]
    float* sc = As + KC * ASTR;
    float* sh = sc + NT;

    int tid = threadIdx.x;
    for (int i = tid; i < K * NT; i += 256) {
        int k = i >> 6, n = i & 63;
        Ws[k * NT + n] = W[n * K + k];
    }
    if (EPI == 2 && tid < NT) {
        float s = ga[tid] * rsqrtf(vv[tid] + BN_EPS_F);
        sc[tid] = s;
        sh[tid] = (bb[tid] - mm[tid]) * s + be[tid];
    }

    int m0 = blockIdx.x * MT;
    int tm = tid >> 4, tn = tid & 15;

    // staging map: lane = row (conflict-free transpose STS); 2 threads per row split k
    int srow = tid & 127;
    int shalf = tid >> 7;
    int gsrow = m0 + srow;
    bool rowOK = gsrow < NN;
    const float4* arow = (const float4*)(Asrc + (size_t)gsrow * K);

    ull acc[4][4];
#pragma unroll
    for (int rp = 0; rp < 4; rp++)
#pragma unroll
        for (int c = 0; c < 4; c++) acc[rp][c] = 0ull;

#pragma unroll
    for (int kc = 0; kc < K / KC; kc++) {
        __syncthreads();
#pragma unroll
        for (int it = shalf * (KC / 8); it < (shalf + 1) * (KC / 8); it++) {
            float4 v = rowOK ? arow[kc * (KC / 4) + it] : make_float4(0.f, 0.f, 0.f, 0.f);
            if (RELU_IN) {
                v.x = fmaxf(v.x, 0.f); v.y = fmaxf(v.y, 0.f);
                v.z = fmaxf(v.z, 0.f); v.w = fmaxf(v.w, 0.f);
            }
            As[(4 * it + 0) * ASTR + srow] = v.x;
            As[(4 * it + 1) * ASTR + srow] = v.y;
            As[(4 * it + 2) * ASTR + srow] = v.z;
            As[(4 * it + 3) * ASTR + srow] = v.w;
        }
        __syncthreads();

        const float* wb = Ws + kc * KC * NT;
#pragma unroll 8
        for (int k = 0; k < KC; k++)
            mk_fma2(acc, As, wb, k, tm, tn);
    }

    if (EPI == 0) {
#pragma unroll
        for (int rp = 0; rp < 4; rp++) {
            float2 p0 = unpk(acc[rp][0]), p1 = unpk(acc[rp][1]);
            float2 p2 = unpk(acc[rp][2]), p3 = unpk(acc[rp][3]);
            int gm = m0 + tm * 8 + 2 * rp;
            if (gm < NN)
                *(float4*)(Yout + (size_t)gm * NT + tn * 4) = make_float4(p0.x, p1.x, p2.x, p3.x);
            if (gm + 1 < NN)
                *(float4*)(Yout + (size_t)(gm + 1) * NT + tn * 4) = make_float4(p0.y, p1.y, p2.y, p3.y);
        }
    } else {
        float4 scv = *(const float4*)(sc + tn * 4);
        float4 shv = *(const float4*)(sh + tn * 4);
#pragma unroll
        for (int rp = 0; rp < 4; rp++) {
            float2 p0 = unpk(acc[rp][0]), p1 = unpk(acc[rp][1]);
            float2 p2 = unpk(acc[rp][2]), p3 = unpk(acc[rp][3]);
            int gm = m0 + tm * 8 + 2 * rp;
            if (gm < NN) {
                int g = batch[gm];
                red_add_v4(out + (size_t)g * NT + tn * 4,
                           fmaxf(fmaf(p0.x, scv.x, shv.x), 0.f),
                           fmaxf(fmaf(p1.x, scv.y, shv.y), 0.f),
                           fmaxf(fmaf(p2.x, scv.z, shv.z), 0.f),
                           fmaxf(fmaf(p3.x, scv.w, shv.w), 0.f));
            }
            if (gm + 1 < NN) {
                int g = batch[gm + 1];
                red_add_v4(out + (size_t)g * NT + tn * 4,
                           fmaxf(fmaf(p0.y, scv.x, shv.x), 0.f),
                           fmaxf(fmaf(p1.y, scv.y, shv.y), 0.f),
                           fmaxf(fmaf(p2.y, scv.z, shv.z), 0.f),
                           fmaxf(fmaf(p3.y, scv.w, shv.w), 0.f));
            }
        }
    }
}

// ---------------------------------------------------------------- k_mid: fused
//   H = relu(bn1(relu(A1) @ W1b^T + b1b));  Y2 = H @ W2a^T -> g_Y
__global__ __launch_bounds__(256, 3) void k_mid(
    const float* __restrict__ W1b, const float* __restrict__ b1b,
    const float* __restrict__ g1,  const float* __restrict__ be1,
    const float* __restrict__ m1,  const float* __restrict__ v1,
    const float* __restrict__ W2a)
{
    extern __shared__ float sm[];
    float* Ws1 = sm;                        // [64][NT]
    float* Ws2 = Ws1 + HID * NT;            // [64][NT]
    float* As  = Ws2 + HID * NT;            // [KC][ASTR]
    float* sc  = As + KC * ASTR;
    float* sh  = sc + NT;

    int tid = threadIdx.x;
    for (int i = tid; i < HID * NT; i += 256) {
        int k = i >> 6, n = i & 63;
        Ws1[k * NT + n] = W1b[n * HID + k];
        Ws2[k * NT + n] = W2a[n * HID + k];
    }
    if (tid < NT) {
        float s = g1[tid] * rsqrtf(v1[tid] + BN_EPS_F);
        sc[tid] = s;
        sh[tid] = (b1b[tid] - m1[tid]) * s + be1[tid];
    }

    int m0 = blockIdx.x * MT;
    int tm = tid >> 4, tn = tid & 15;

    int srow = tid & 127;
    int shalf = tid >> 7;
    int gsrow = m0 + srow;
    bool rowOK = gsrow < NN;
    const float4* arow = (const float4*)(g_A + (size_t)gsrow * HID);

    // stage relu(A1) transposed (lane = row, conflict-free)
#pragma unroll
    for (int it = shalf * (KC / 8); it < (shalf + 1) * (KC / 8); it++) {
        float4 v = rowOK ? arow[it] : make_float4(0.f, 0.f, 0.f, 0.f);
        v.x = fmaxf(v.x, 0.f); v.y = fmaxf(v.y, 0.f);
        v.z = fmaxf(v.z, 0.f); v.w = fmaxf(v.w, 0.f);
        As[(4 * it + 0) * ASTR + srow] = v.x;
        As[(4 * it + 1) * ASTR + srow] = v.y;
        As[(4 * it + 2) * ASTR + srow] = v.z;
        As[(4 * it + 3) * ASTR + srow] = v.w;
    }
    __syncthreads();

    ull acc[4][4];
#pragma unroll
    for (int rp = 0; rp < 4; rp++)
#pragma unroll
        for (int c = 0; c < 4; c++) acc[rp][c] = 0ull;

    // phase 1
#pragma unroll 8
    for (int k = 0; k < KC; k++)
        mk_fma2(acc, As, Ws1, k, tm, tn);
    __syncthreads();

    // bn1+relu -> write H tile back into As as [n][m]; pairs store as ulonglong2
#pragma unroll
    for (int c = 0; c < 4; c++) {
        int n = tn * 4 + c;
        float s = sc[n], t = sh[n];
        float2 q0 = unpk(acc[0][c]), q1 = unpk(acc[1][c]);
        float2 q2 = unpk(acc[2][c]), q3 = unpk(acc[3][c]);
        float4 v0 = make_float4(fmaxf(fmaf(q0.x, s, t), 0.f), fmaxf(fmaf(q0.y, s, t), 0.f),
                                fmaxf(fmaf(q1.x, s, t), 0.f), fmaxf(fmaf(q1.y, s, t), 0.f));
        float4 v1 = make_float4(fmaxf(fmaf(q2.x, s, t), 0.f), fmaxf(fmaf(q2.y, s, t), 0.f),
                                fmaxf(fmaf(q3.x, s, t), 0.f), fmaxf(fmaf(q3.y, s, t), 0.f));
        *(float4*)(As + n * ASTR + tm * 8) = v0;
        *(float4*)(As + n * ASTR + tm * 8 + 4) = v1;
    }
    __syncthreads();

    // phase 2
#pragma unroll
    for (int rp = 0; rp < 4; rp++)
#pragma unroll
        for (int c = 0; c < 4; c++) acc[rp][c] = 0ull;

#pragma unroll 8
    for (int k = 0; k < KC; k++)
        mk_fma2(acc, As, Ws2, k, tm, tn);

#pragma unroll
    for (int rp = 0; rp < 4; rp++) {
        float2 p0 = unpk(acc[rp][0]), p1 = unpk(acc[rp][1]);
        float2 p2 = unpk(acc[rp][2]), p3 = unpk(acc[rp][3]);
        int gm = m0 + tm * 8 + 2 * rp;
        if (gm < NN)
            *(float4*)(g_Y + (size_t)gm * HID + tn * 4) = make_float4(p0.x, p1.x, p2.x, p3.x);
        if (gm + 1 < NN)
            *(float4*)(g_Y + (size_t)(gm + 1) * HID + tn * 4) = make_float4(p0.y, p1.y, p2.y, p3.y);
    }
}

// ------------------------------------------------- divide by per-graph counts
__global__ void k_div(const int* __restrict__ batch, float* __restrict__ out)
{
    int g = blockIdx.x;
    __shared__ int cnt;
    if (threadIdx.x == 0) {
        int lo = 0, hi = NN;
        while (lo < hi) { int mid = (lo + hi) >> 1; if (batch[mid] < g) lo = mid + 1; else hi = mid; }
        int lo2 = lo, hi2 = NN;
        while (lo2 < hi2) { int mid = (lo2 + hi2) >> 1; if (batch[mid] < g + 1) lo2 = mid + 1; else hi2 = mid; }
        cnt = lo2 - lo;
    }
    __syncthreads();
    float c = (float)(cnt > 1 ? cnt : 1);
    out[(size_t)g * HID + threadIdx.x] /= c;
}

// ---------------------------------------------------------------- launch
extern "C" void kernel_launch(void* const* d_in, const int* in_sizes, int n_in,
                              void* d_out, int out_size)
{
    (void)in_sizes; (void)n_in; (void)out_size;
    const float* x    = (const float*)d_in[0];
    const int*   ei   = (const int*)d_in[1];
    const int*   batch= (const int*)d_in[2];
    const float* W1a  = (const float*)d_in[3];
    const float* b1a  = (const float*)d_in[4];
    const float* W1b  = (const float*)d_in[5];
    const float* b1b  = (const float*)d_in[6];
    const float* g1   = (const float*)d_in[7];
    const float* be1  = (const float*)d_in[8];
    const float* m1   = (const float*)d_in[9];
    const float* v1   = (const float*)d_in[10];
    const float* W2a  = (const float*)d_in[11];
    const float* b2a  = (const float*)d_in[12];
    const float* W2b  = (const float*)d_in[13];
    const float* b2b  = (const float*)d_in[14];
    const float* g2   = (const float*)d_in[15];
    const float* be2  = (const float*)d_in[16];
    const float* m2   = (const float*)d_in[17];
    const float* v2   = (const float*)d_in[18];
    float* out = (float*)d_out;

    float* yP;  cudaGetSymbolAddress((void**)&yP, g_Y);
    float* aP;  cudaGetSymbolAddress((void**)&aP, g_A);

    const int smem64  = (HID * NT + KC * ASTR + 2 * NT) * (int)sizeof(float);      // ~50.7KB
    const int smem128 = (FIN * NT + KC * ASTR + 2 * NT) * (int)sizeof(float);      // ~67.1KB
    const int smemMid = (2 * HID * NT + KC * ASTR + 2 * NT) * (int)sizeof(float);  // ~67.1KB
    cudaFuncSetAttribute(k_gemm<FIN, false, 0>, cudaFuncAttributeMaxDynamicSharedMemorySize, smem128);
    cudaFuncSetAttribute(k_mid,                 cudaFuncAttributeMaxDynamicSharedMemorySize, smemMid);
    cudaFuncSetAttribute(k_gemm<HID, true, 2>,  cudaFuncAttributeMaxDynamicSharedMemorySize, smem64);

    int gemmBlocks = (NN + MT - 1) / MT;           // 782
    int edgeBlocks = (EE + 255) / 256;             // 6250
    int aggBlocks  = (NN * 16 + 255) / 256;        // 6250

    k_zero_all<<<(NN + 255) / 256, 256>>>(out);
    k_hist<<<edgeBlocks, 256>>>(ei);
    k_scan1<<<NCHUNK, SCAN_CHUNK>>>();
    // slot 4 (profiled): K=128 GEMM — dependency-free w.r.t. CSR chain
    k_gemm<FIN, false, 0><<<gemmBlocks, 256, smem128>>>(
        x, W1a, yP, nullptr, nullptr, nullptr, nullptr, nullptr, nullptr, nullptr);
    k_scan3f<<<(NN + 255) / 256, 256>>>();
    k_reorder<<<edgeBlocks, 256>>>(ei);

    // layer 1 + mid
    k_agg<<<aggBlocks, 256>>>(b1a);
    k_mid<<<gemmBlocks, 256, smemMid>>>(W1b, b1b, g1, be1, m1, v1, W2a);

    // layer 2
    k_agg<<<aggBlocks, 256>>>(b2a);
    k_gemm<HID, true, 2><<<gemmBlocks, 256, smem64>>>(
        aP, W2b, nullptr, b2b, g2, be2, m2, v2, batch, out);
    k_div<<<NG, HID>>>(batch, out);
}

// round 9
// speedup vs baseline: 1.1687x; 1.0903x over previous
#include <cuda_runtime.h>
#include <cuda_bf16.h>
#include <cstdint>

#define NN 100000
#define EE 1600000
#define FIN 128
#define HID 64
#define NG 512
#define BN_EPS_F 1e-5f

#define SCAN_CHUNK 1024
#define NCHUNK ((NN + SCAN_CHUNK - 1) / SCAN_CHUNK)   // 98

// FFMA2 GEMM tiling (k_mid / k_final, unchanged from round 7)
#define MT 128
#define NT 64
#define KC 64
#define ASTR 132

// mma.sync in_proj tile: SMEM bf16 rows padded to 136 elems = 272B
#define RSTRB 272
#define XH_OFF 0
#define XL_OFF 34816
#define WH_OFF 69632
#define WL_OFF 87040
#define MMA_SMEM 104448

typedef unsigned long long ull;

// Scratch (allocation-free rule: __device__ globals).
__device__ __align__(16) float g_Y[(size_t)NN * HID];
__device__ __align__(16) float g_A[(size_t)NN * HID];
__device__ int g_cnt[NN];
__device__ int g_scan[NN];
__device__ int g_bsum[NCHUNK];
__device__ int g_rowptr[NN + 1];
__device__ int g_cursor[NN];
__device__ int g_ss[EE];

__device__ __forceinline__ void red_add_v4(float* p, float a, float b, float c, float d) {
    asm volatile("red.global.add.v4.f32 [%0], {%1,%2,%3,%4};"
                 :: "l"(p), "f"(a), "f"(b), "f"(c), "f"(d) : "memory");
}

// ---- packed f32x2 helpers
__device__ __forceinline__ ull splat2(float x) {
    ull r; asm("mov.b64 %0, {%1, %1};" : "=l"(r) : "f"(x)); return r;
}
__device__ __forceinline__ void fma2(ull& d, ull a, ull b) {
    asm("fma.rn.f32x2 %0, %1, %2, %0;" : "+l"(d) : "l"(a), "l"(b));
}
__device__ __forceinline__ float2 unpk(ull v) {
    float2 f; asm("mov.b64 {%0, %1}, %2;" : "=f"(f.x), "=f"(f.y) : "l"(v)); return f;
}

__device__ __forceinline__ uint32_t smem_u32(const void* p) {
    uint32_t a;
    asm("{ .reg .u64 t; cvta.to.shared.u64 t, %1; cvt.u32.u64 %0, t; }" : "=r"(a) : "l"(p));
    return a;
}
// pack two floats -> bf16x2 (first arg -> low 16 bits)
#define BF2(res, a, b) asm("cvt.rn.satfinite.bf16x2.f32 %0, %1, %2;" : "=r"(res) : "f"(b), "f"(a))

#define LDMX4(r0, r1, r2, r3, addr)                                             \
    asm volatile("ldmatrix.sync.aligned.m8n8.x4.shared.b16 {%0,%1,%2,%3}, [%4];" \
                 : "=r"(r0), "=r"(r1), "=r"(r2), "=r"(r3) : "r"(addr))

#define MMA16816(d, a0, a1, a2, a3, b0, b1)                                     \
    asm volatile("mma.sync.aligned.m16n8k16.row.col.f32.bf16.bf16.f32 "         \
                 "{%0,%1,%2,%3}, {%4,%5,%6,%7}, {%8,%9}, {%0,%1,%2,%3};"        \
                 : "+f"((d)[0]), "+f"((d)[1]), "+f"((d)[2]), "+f"((d)[3])       \
                 : "r"(a0), "r"(a1), "r"(a2), "r"(a3), "r"(b0), "r"(b1))

// ---------------------------------------------------------------- fused zero
__global__ void k_zero_all(float* __restrict__ out) {
    int i = blockIdx.x * blockDim.x + threadIdx.x;
    if (i < NG * HID) out[i] = 0.f;
    if (i < NN) g_cnt[i] = 0;
}

// ---------------------------------------------------------------- CSR build
__global__ void k_hist(const int* __restrict__ ei) {
    int e = blockIdx.x * blockDim.x + threadIdx.x;
    if (e < EE) atomicAdd(&g_cnt[ei[EE + e]], 1);
}

__global__ __launch_bounds__(SCAN_CHUNK) void k_scan1() {
    __shared__ int s[SCAN_CHUNK];
    int tid = threadIdx.x;
    int i = blockIdx.x * SCAN_CHUNK + tid;
    int v = (i < NN) ? g_cnt[i] : 0;
    s[tid] = v;
    __syncthreads();
#pragma unroll
    for (int off = 1; off < SCAN_CHUNK; off <<= 1) {
        int t = (tid >= off) ? s[tid - off] : 0;
        __syncthreads();
        s[tid] += t;
        __syncthreads();
    }
    if (i < NN) g_scan[i] = s[tid];
    if (tid == SCAN_CHUNK - 1) g_bsum[blockIdx.x] = s[tid];
}

__global__ void k_scan3f() {
    __shared__ int boff[NCHUNK];
    if (threadIdx.x == 0) {
        int run = 0;
#pragma unroll 2
        for (int c = 0; c < NCHUNK; c++) { int t = g_bsum[c]; boff[c] = run; run += t; }
    }
    __syncthreads();
    int i = blockIdx.x * blockDim.x + threadIdx.x;
    if (i >= NN) return;
    int incl = g_scan[i] + boff[i / SCAN_CHUNK];
    g_rowptr[i + 1] = incl;
    g_cursor[i] = incl - g_cnt[i];
    if (i == 0) g_rowptr[0] = 0;
}

__global__ void k_reorder(const int* __restrict__ ei) {
    int e = blockIdx.x * blockDim.x + threadIdx.x;
    if (e >= EE) return;
    int d = ei[EE + e];
    int pos = atomicAdd(&g_cursor[d], 1);
    g_ss[pos] = ei[e];
}

// ---------------------------------------------------------------- aggregation
__global__ __launch_bounds__(256) void k_agg(const float* __restrict__ b) {
    int t = blockIdx.x * 256 + threadIdx.x;
    int n = t >> 4;
    int lane = t & 15;
    if (n >= NN) return;

    const float4* Y4 = (const float4*)g_Y;
    float4 bv = ((const float4*)b)[lane];
    float4 acc = Y4[(size_t)n * 16 + lane];
    acc.x += bv.x; acc.y += bv.y; acc.z += bv.z; acc.w += bv.w;

    int beg = g_rowptr[n], end = g_rowptr[n + 1];
#pragma unroll 4
    for (int e = beg; e < end; e++) {
        int s = g_ss[e];
        float4 v = Y4[(size_t)s * 16 + lane];
        acc.x += v.x; acc.y += v.y; acc.z += v.z; acc.w += v.w;
    }
    ((float4*)g_A)[(size_t)n * 16 + lane] = acc;
}

// ================================================================ in_proj via mma.sync (bf16 split)
// Y[128 x 64] = x[128 x 128] @ W^T; warp w owns m-rows 16w..16w+15, all 64 cols.
__global__ __launch_bounds__(256, 2) void k_in_proj_mma(
    const float* __restrict__ x, const float* __restrict__ W)
{
    extern __shared__ char smc[];
    uint32_t sb = smem_u32(smc);
    int tid = threadIdx.x;
    int w = tid >> 5, l = tid & 31;
    int m0 = blockIdx.x * 128;

    // ---- stage A (x) as bf16 hi/lo: thread = (row, half of k)
    {
        int row = tid >> 1, half = tid & 1;
        int gm = m0 + row;
        bool ok = gm < NN;
        const float4* xr = (const float4*)(x + (size_t)gm * FIN + half * 64);
        int rbase = row * RSTRB + half * 128;
#pragma unroll
        for (int c = 0; c < 8; c++) {
            float4 f0 = ok ? xr[2 * c] : make_float4(0.f, 0.f, 0.f, 0.f);
            float4 f1 = ok ? xr[2 * c + 1] : make_float4(0.f, 0.f, 0.f, 0.f);
            float fv[8] = {f0.x, f0.y, f0.z, f0.w, f1.x, f1.y, f1.z, f1.w};
            uint32_t hp[4], lp[4];
#pragma unroll
            for (int j = 0; j < 4; j++) {
                BF2(hp[j], fv[2 * j], fv[2 * j + 1]);
                float l0 = fv[2 * j]     - __uint_as_float(hp[j] << 16);
                float l1 = fv[2 * j + 1] - __uint_as_float(hp[j] & 0xFFFF0000u);
                BF2(lp[j], l0, l1);
            }
            *(uint4*)(smc + XH_OFF + rbase + c * 16) = make_uint4(hp[0], hp[1], hp[2], hp[3]);
            *(uint4*)(smc + XL_OFF + rbase + c * 16) = make_uint4(lp[0], lp[1], lp[2], lp[3]);
        }
    }
    // ---- stage W as bf16 hi/lo: thread = (row, quarter of k)
    {
        int row = tid >> 2, q = tid & 3;
        const float4* wr = (const float4*)(W + (size_t)row * FIN + q * 32);
        int rbase = row * RSTRB + q * 64;
#pragma unroll
        for (int c = 0; c < 4; c++) {
            float4 f0 = wr[2 * c];
            float4 f1 = wr[2 * c + 1];
            float fv[8] = {f0.x, f0.y, f0.z, f0.w, f1.x, f1.y, f1.z, f1.w};
            uint32_t hp[4], lp[4];
#pragma unroll
            for (int j = 0; j < 4; j++) {
                BF2(hp[j], fv[2 * j], fv[2 * j + 1]);
                float l0 = fv[2 * j]     - __uint_as_float(hp[j] << 16);
                float l1 = fv[2 * j + 1] - __uint_as_float(hp[j] & 0xFFFF0000u);
                BF2(lp[j], l0, l1);
            }
            *(uint4*)(smc + WH_OFF + rbase + c * 16) = make_uint4(hp[0], hp[1], hp[2], hp[3]);
            *(uint4*)(smc + WL_OFF + rbase + c * 16) = make_uint4(lp[0], lp[1], lp[2], lp[3]);
        }
    }
    __syncthreads();

    // ---- per-lane ldmatrix base addresses
    // A x4: matrices [m0-7,k0-7],[m8-15,k0-7],[m0-7,k8-15],[m8-15,k8-15]
    uint32_t aAddr = sb + (uint32_t)((16 * w + (l & 15)) * RSTRB + (l >> 4) * 16);
    // B x4 (2 n-chunks): [n0-7,k0-7],[n0-7,k8-15],[n8-15,k0-7],[n8-15,k8-15]
    int bN = (l & 7) + ((l >> 4) << 3);
    int bKc = (l >> 3) & 1;
    uint32_t bAddr = sb + (uint32_t)(bN * RSTRB + bKc * 16);

    float D[8][4];
#pragma unroll
    for (int nc = 0; nc < 8; nc++)
#pragma unroll
        for (int j = 0; j < 4; j++) D[nc][j] = 0.f;

#pragma unroll
    for (int ks = 0; ks < 8; ks++) {
        uint32_t ko = ks * 32;
        uint32_t ah0, ah1, ah2, ah3, al0, al1, al2, al3;
        LDMX4(ah0, ah1, ah2, ah3, aAddr + XH_OFF + ko);
        LDMX4(al0, al1, al2, al3, aAddr + XL_OFF + ko);
#pragma unroll
        for (int g = 0; g < 4; g++) {
            uint32_t gb = bAddr + (uint32_t)(g * 16 * RSTRB) + ko;
            uint32_t bh0, bh1, bh2, bh3, bl0, bl1, bl2, bl3;
            LDMX4(bh0, bh1, bh2, bh3, gb + WH_OFF);
            LDMX4(bl0, bl1, bl2, bl3, gb + WL_OFF);
            MMA16816(D[2 * g],     ah0, ah1, ah2, ah3, bh0, bh1);
            MMA16816(D[2 * g],     ah0, ah1, ah2, ah3, bl0, bl1);
            MMA16816(D[2 * g],     al0, al1, al2, al3, bh0, bh1);
            MMA16816(D[2 * g + 1], ah0, ah1, ah2, ah3, bh2, bh3);
            MMA16816(D[2 * g + 1], ah0, ah1, ah2, ah3, bl2, bl3);
            MMA16816(D[2 * g + 1], al0, al1, al2, al3, bh2, bh3);
        }
    }

    // ---- epilogue: D frag (m16n8): thread holds rows (l>>2, l>>2+8), cols 2(l&3)+{0,1}
    int r0 = m0 + 16 * w + (l >> 2);
    int r1 = r0 + 8;
#pragma unroll
    for (int nc = 0; nc < 8; nc++) {
        int col = nc * 8 + (l & 3) * 2;
        if (r0 < NN) *(float2*)(g_Y + (size_t)r0 * HID + col) = make_float2(D[nc][0], D[nc][1]);
        if (r1 < NN) *(float2*)(g_Y + (size_t)r1 * HID + col) = make_float2(D[nc][2], D[nc][3]);
    }
}

// ---------------------------------------------------------------- f32x2 micro-kernel
__device__ __forceinline__ void mk_fma2(ull acc[4][4], const float* As, const float* wb,
                                        int k, int tm, int tn)
{
    ulonglong2 a01 = *(const ulonglong2*)(As + k * ASTR + tm * 8);
    ulonglong2 a23 = *(const ulonglong2*)(As + k * ASTR + tm * 8 + 4);
    float4 w = *(const float4*)(wb + k * NT + tn * 4);
    ull av[4] = {a01.x, a01.y, a23.x, a23.y};
    ull wv[4] = {splat2(w.x), splat2(w.y), splat2(w.z), splat2(w.w)};
#pragma unroll
    for (int rp = 0; rp < 4; rp++)
#pragma unroll
        for (int c = 0; c < 4; c++)
            fma2(acc[rp][c], av[rp], wv[c]);
}

// ---------------------------------------------------------------- tiled GEMM (final pool)
template<int K, bool RELU_IN, int EPI>
__global__ __launch_bounds__(256, 3) void k_gemm(
    const float* __restrict__ Asrc, const float* __restrict__ W,
    float* __restrict__ Yout,
    const float* __restrict__ bb, const float* __restrict__ ga,
    const float* __restrict__ be, const float* __restrict__ mm,
    const float* __restrict__ vv,
    const int* __restrict__ batch, float* __restrict__ out)
{
    extern __shared__ float sm[];
    float* Ws = sm;
    float* As = Ws + K * NT;
    float* sc = As + KC * ASTR;
    float* sh = sc + NT;

    int tid = threadIdx.x;
    for (int i = tid; i < K * NT; i += 256) {
        int k = i >> 6, n = i & 63;
        Ws[k * NT + n] = W[n * K + k];
    }
    if (EPI == 2 && tid < NT) {
        float s = ga[tid] * rsqrtf(vv[tid] + BN_EPS_F);
        sc[tid] = s;
        sh[tid] = (bb[tid] - mm[tid]) * s + be[tid];
    }

    int m0 = blockIdx.x * MT;
    int tm = tid >> 4, tn = tid & 15;

    int srow = tid & 127;
    int shalf = tid >> 7;
    int gsrow = m0 + srow;
    bool rowOK = gsrow < NN;
    const float4* arow = (const float4*)(Asrc + (size_t)gsrow * K);

    ull acc[4][4];
#pragma unroll
    for (int rp = 0; rp < 4; rp++)
#pragma unroll
        for (int c = 0; c < 4; c++) acc[rp][c] = 0ull;

#pragma unroll
    for (int kc = 0; kc < K / KC; kc++) {
        __syncthreads();
#pragma unroll
        for (int it = shalf * (KC / 8); it < (shalf + 1) * (KC / 8); it++) {
            float4 v = rowOK ? arow[kc * (KC / 4) + it] : make_float4(0.f, 0.f, 0.f, 0.f);
            if (RELU_IN) {
                v.x = fmaxf(v.x, 0.f); v.y = fmaxf(v.y, 0.f);
                v.z = fmaxf(v.z, 0.f); v.w = fmaxf(v.w, 0.f);
            }
            As[(4 * it + 0) * ASTR + srow] = v.x;
            As[(4 * it + 1) * ASTR + srow] = v.y;
            As[(4 * it + 2) * ASTR + srow] = v.z;
            As[(4 * it + 3) * ASTR + srow] = v.w;
        }
        __syncthreads();

        const float* wb = Ws + kc * KC * NT;
#pragma unroll 8
        for (int k = 0; k < KC; k++)
            mk_fma2(acc, As, wb, k, tm, tn);
    }

    if (EPI == 0) {
#pragma unroll
        for (int rp = 0; rp < 4; rp++) {
            float2 p0 = unpk(acc[rp][0]), p1 = unpk(acc[rp][1]);
            float2 p2 = unpk(acc[rp][2]), p3 = unpk(acc[rp][3]);
            int gm = m0 + tm * 8 + 2 * rp;
            if (gm < NN)
                *(float4*)(Yout + (size_t)gm * NT + tn * 4) = make_float4(p0.x, p1.x, p2.x, p3.x);
            if (gm + 1 < NN)
                *(float4*)(Yout + (size_t)(gm + 1) * NT + tn * 4) = make_float4(p0.y, p1.y, p2.y, p3.y);
        }
    } else {
        float4 scv = *(const float4*)(sc + tn * 4);
        float4 shv = *(const float4*)(sh + tn * 4);
#pragma unroll
        for (int rp = 0; rp < 4; rp++) {
            float2 p0 = unpk(acc[rp][0]), p1 = unpk(acc[rp][1]);
            float2 p2 = unpk(acc[rp][2]), p3 = unpk(acc[rp][3]);
            int gm = m0 + tm * 8 + 2 * rp;
            if (gm < NN) {
                int g = batch[gm];
                red_add_v4(out + (size_t)g * NT + tn * 4,
                           fmaxf(fmaf(p0.x, scv.x, shv.x), 0.f),
                           fmaxf(fmaf(p1.x, scv.y, shv.y), 0.f),
                           fmaxf(fmaf(p2.x, scv.z, shv.z), 0.f),
                           fmaxf(fmaf(p3.x, scv.w, shv.w), 0.f));
            }
            if (gm + 1 < NN) {
                int g = batch[gm + 1];
                red_add_v4(out + (size_t)g * NT + tn * 4,
                           fmaxf(fmaf(p0.y, scv.x, shv.x), 0.f),
                           fmaxf(fmaf(p1.y, scv.y, shv.y), 0.f),
                           fmaxf(fmaf(p2.y, scv.z, shv.z), 0.f),
                           fmaxf(fmaf(p3.y, scv.w, shv.w), 0.f));
            }
        }
    }
}

// ---------------------------------------------------------------- k_mid (unchanged)
__global__ __launch_bounds__(256, 3) void k_mid(
    const float* __restrict__ W1b, const float* __restrict__ b1b,
    const float* __restrict__ g1,  const float* __restrict__ be1,
    const float* __restrict__ m1,  const float* __restrict__ v1,
    const float* __restrict__ W2a)
{
    extern __shared__ float sm[];
    float* Ws1 = sm;
    float* Ws2 = Ws1 + HID * NT;
    float* As  = Ws2 + HID * NT;
    float* sc  = As + KC * ASTR;
    float* sh  = sc + NT;

    int tid = threadIdx.x;
    for (int i = tid; i < HID * NT; i += 256) {
        int k = i >> 6, n = i & 63;
        Ws1[k * NT + n] = W1b[n * HID + k];
        Ws2[k * NT + n] = W2a[n * HID + k];
    }
    if (tid < NT) {
        float s = g1[tid] * rsqrtf(v1[tid] + BN_EPS_F);
        sc[tid] = s;
        sh[tid] = (b1b[tid] - m1[tid]) * s + be1[tid];
    }

    int m0 = blockIdx.x * MT;
    int tm = tid >> 4, tn = tid & 15;

    int srow = tid & 127;
    int shalf = tid >> 7;
    int gsrow = m0 + srow;
    bool rowOK = gsrow < NN;
    const float4* arow = (const float4*)(g_A + (size_t)gsrow * HID);

#pragma unroll
    for (int it = shalf * (KC / 8); it < (shalf + 1) * (KC / 8); it++) {
        float4 v = rowOK ? arow[it] : make_float4(0.f, 0.f, 0.f, 0.f);
        v.x = fmaxf(v.x, 0.f); v.y = fmaxf(v.y, 0.f);
        v.z = fmaxf(v.z, 0.f); v.w = fmaxf(v.w, 0.f);
        As[(4 * it + 0) * ASTR + srow] = v.x;
        As[(4 * it + 1) * ASTR + srow] = v.y;
        As[(4 * it + 2) * ASTR + srow] = v.z;
        As[(4 * it + 3) * ASTR + srow] = v.w;
    }
    __syncthreads();

    ull acc[4][4];
#pragma unroll
    for (int rp = 0; rp < 4; rp++)
#pragma unroll
        for (int c = 0; c < 4; c++) acc[rp][c] = 0ull;

#pragma unroll 8
    for (int k = 0; k < KC; k++)
        mk_fma2(acc, As, Ws1, k, tm, tn);
    __syncthreads();

#pragma unroll
    for (int c = 0; c < 4; c++) {
        int n = tn * 4 + c;
        float s = sc[n], t = sh[n];
        float2 q0 = unpk(acc[0][c]), q1 = unpk(acc[1][c]);
        float2 q2 = unpk(acc[2][c]), q3 = unpk(acc[3][c]);
        float4 v0 = make_float4(fmaxf(fmaf(q0.x, s, t), 0.f), fmaxf(fmaf(q0.y, s, t), 0.f),
                                fmaxf(fmaf(q1.x, s, t), 0.f), fmaxf(fmaf(q1.y, s, t), 0.f));
        float4 v1 = make_float4(fmaxf(fmaf(q2.x, s, t), 0.f), fmaxf(fmaf(q2.y, s, t), 0.f),
                                fmaxf(fmaf(q3.x, s, t), 0.f), fmaxf(fmaf(q3.y, s, t), 0.f));
        *(float4*)(As + n * ASTR + tm * 8) = v0;
        *(float4*)(As + n * ASTR + tm * 8 + 4) = v1;
    }
    __syncthreads();

#pragma unroll
    for (int rp = 0; rp < 4; rp++)
#pragma unroll
        for (int c = 0; c < 4; c++) acc[rp][c] = 0ull;

#pragma unroll 8
    for (int k = 0; k < KC; k++)
        mk_fma2(acc, As, Ws2, k, tm, tn);

#pragma unroll
    for (int rp = 0; rp < 4; rp++) {
        float2 p0 = unpk(acc[rp][0]), p1 = unpk(acc[rp][1]);
        float2 p2 = unpk(acc[rp][2]), p3 = unpk(acc[rp][3]);
        int gm = m0 + tm * 8 + 2 * rp;
        if (gm < NN)
            *(float4*)(g_Y + (size_t)gm * HID + tn * 4) = make_float4(p0.x, p1.x, p2.x, p3.x);
        if (gm + 1 < NN)
            *(float4*)(g_Y + (size_t)(gm + 1) * HID + tn * 4) = make_float4(p0.y, p1.y, p2.y, p3.y);
    }
}

// ------------------------------------------------- divide by per-graph counts
__global__ void k_div(const int* __restrict__ batch, float* __restrict__ out)
{
    int g = blockIdx.x;
    __shared__ int cnt;
    if (threadIdx.x == 0) {
        int lo = 0, hi = NN;
        while (lo < hi) { int mid = (lo + hi) >> 1; if (batch[mid] < g) lo = mid + 1; else hi = mid; }
        int lo2 = lo, hi2 = NN;
        while (lo2 < hi2) { int mid = (lo2 + hi2) >> 1; if (batch[mid] < g + 1) lo2 = mid + 1; else hi2 = mid; }
        cnt = lo2 - lo;
    }
    __syncthreads();
    float c = (float)(cnt > 1 ? cnt : 1);
    out[(size_t)g * HID + threadIdx.x] /= c;
}

// ---------------------------------------------------------------- launch
extern "C" void kernel_launch(void* const* d_in, const int* in_sizes, int n_in,
                              void* d_out, int out_size)
{
    (void)in_sizes; (void)n_in; (void)out_size;
    const float* x    = (const float*)d_in[0];
    const int*   ei   = (const int*)d_in[1];
    const int*   batch= (const int*)d_in[2];
    const float* W1a  = (const float*)d_in[3];
    const float* b1a  = (const float*)d_in[4];
    const float* W1b  = (const float*)d_in[5];
    const float* b1b  = (const float*)d_in[6];
    const float* g1   = (const float*)d_in[7];
    const float* be1  = (const float*)d_in[8];
    const float* m1   = (const float*)d_in[9];
    const float* v1   = (const float*)d_in[10];
    const float* W2a  = (const float*)d_in[11];
    const float* b2a  = (const float*)d_in[12];
    const float* W2b  = (const float*)d_in[13];
    const float* b2b  = (const float*)d_in[14];
    const float* g2   = (const float*)d_in[15];
    const float* be2  = (const float*)d_in[16];
    const float* m2   = (const float*)d_in[17];
    const float* v2   = (const float*)d_in[18];
    float* out = (float*)d_out;

    float* aP;  cudaGetSymbolAddress((void**)&aP, g_A);

    const int smem64  = (HID * NT + KC * ASTR + 2 * NT) * (int)sizeof(float);
    const int smemMid = (2 * HID * NT + KC * ASTR + 2 * NT) * (int)sizeof(float);
    cudaFuncSetAttribute(k_in_proj_mma, cudaFuncAttributeMaxDynamicSharedMemorySize, MMA_SMEM);
    cudaFuncSetAttribute(k_mid,         cudaFuncAttributeMaxDynamicSharedMemorySize, smemMid);
    cudaFuncSetAttribute(k_gemm<HID, true, 2>, cudaFuncAttributeMaxDynamicSharedMemorySize, smem64);

    int gemmBlocks = (NN + MT - 1) / MT;           // 782
    int edgeBlocks = (EE + 255) / 256;             // 6250
    int aggBlocks  = (NN * 16 + 255) / 256;        // 6250

    k_zero_all<<<(NN + 255) / 256, 256>>>(out);
    k_hist<<<edgeBlocks, 256>>>(ei);
    k_scan1<<<NCHUNK, SCAN_CHUNK>>>();
    // slot 4 (profiled): mma.sync in_proj — dependency-free w.r.t. CSR chain
    k_in_proj_mma<<<gemmBlocks, 256, MMA_SMEM>>>(x, W1a);
    k_scan3f<<<(NN + 255) / 256, 256>>>();
    k_reorder<<<edgeBlocks, 256>>>(ei);

    // layer 1 + mid
    k_agg<<<aggBlocks, 256>>>(b1a);
    k_mid<<<gemmBlocks, 256, smemMid>>>(W1b, b1b, g1, be1, m1, v1, W2a);

    // layer 2
    k_agg<<<aggBlocks, 256>>>(b2a);
    k_gemm<HID, true, 2><<<gemmBlocks, 256, smem64>>>(
        aP, W2b, nullptr, b2b, g2, be2, m2, v2, batch, out);
    k_div<<<NG, HID>>>(batch, out);
}

// round 11
// speedup vs baseline: 1.4457x; 1.2370x over previous
#include <cuda_runtime.h>
#include <cuda_bf16.h>
#include <cstdint>

#define NN 100000
#define EE 1600000
#define FIN 128
#define HID 64
#define NG 512
#define BN_EPS_F 1e-5f

#define SCAN_CHUNK 1024
#define NCHUNK ((NN + SCAN_CHUNK - 1) / SCAN_CHUNK)   // 98

// mma.sync in_proj tile: SMEM bf16 rows padded (K=128 -> 136 elems = 272B)
#define RSTRB 272
#define XH_OFF 0
#define XL_OFF 34816
#define WH_OFF 69632
#define WL_OFF 87040
#define MMA_SMEM 104448

// K=64 mma tiles (mid / final): bf16 rows padded to 72 elems = 144B
#define RST2 144
// k_mid smem layout (bytes)
#define MD_AH 0
#define MD_AL 18432
#define MD_W1H 36864
#define MD_W1L 46080
#define MD_W2H 55296
#define MD_W2L 64512
#define MD_SC 73728
#define MD_SH 73984
#define MD_SMEM 74240
// k_final smem layout
#define FN_AH 0
#define FN_AL 18432
#define FN_WH 36864
#define FN_WL 46080
#define FN_SC 55296
#define FN_SH 55552
#define FN_SMEM 55808

typedef unsigned long long ull;

// Scratch (allocation-free rule: __device__ globals).
__device__ __align__(16) float g_Y[(size_t)NN * HID];
__device__ __align__(16) float g_A[(size_t)NN * HID];
__device__ int g_cnt[NN];
__device__ int g_scan[NN];
__device__ int g_bsum[NCHUNK];
__device__ int g_rowptr[NN + 1];
__device__ int g_cursor[NN];
__device__ int g_ss[EE];

__device__ __forceinline__ void red_add_v2(float* p, float a, float b) {
    asm volatile("red.global.add.v2.f32 [%0], {%1,%2};"
                 :: "l"(p), "f"(a), "f"(b) : "memory");
}

__device__ __forceinline__ uint32_t smem_u32(const void* p) {
    uint32_t a;
    asm("{ .reg .u64 t; cvta.to.shared.u64 t, %1; cvt.u32.u64 %0, t; }" : "=r"(a) : "l"(p));
    return a;
}
// pack two floats -> bf16x2 (first arg -> low 16 bits)
#define BF2(res, a, b) asm("cvt.rn.satfinite.bf16x2.f32 %0, %1, %2;" : "=r"(res) : "f"(b), "f"(a))

#define LDMX4(r0, r1, r2, r3, addr)                                             \
    asm volatile("ldmatrix.sync.aligned.m8n8.x4.shared.b16 {%0,%1,%2,%3}, [%4];" \
                 : "=r"(r0), "=r"(r1), "=r"(r2), "=r"(r3) : "r"(addr))

#define MMA16816(d, a0, a1, a2, a3, b0, b1)                                     \
    asm volatile("mma.sync.aligned.m16n8k16.row.col.f32.bf16.bf16.f32 "         \
                 "{%0,%1,%2,%3}, {%4,%5,%6,%7}, {%8,%9}, {%0,%1,%2,%3};"        \
                 : "+f"((d)[0]), "+f"((d)[1]), "+f"((d)[2]), "+f"((d)[3])       \
                 : "r"(a0), "r"(a1), "r"(a2), "r"(a3), "r"(b0), "r"(b1))

// split 8 floats into bf16x2 hi/lo quads
__device__ __forceinline__ void split8(const float* fv, uint32_t* hp, uint32_t* lp) {
#pragma unroll
    for (int j = 0; j < 4; j++) {
        BF2(hp[j], fv[2 * j], fv[2 * j + 1]);
        float l0 = fv[2 * j]     - __uint_as_float(hp[j] << 16);
        float l1 = fv[2 * j + 1] - __uint_as_float(hp[j] & 0xFFFF0000u);
        BF2(lp[j], l0, l1);
    }
}

// ---------------------------------------------------------------- fused zero
__global__ void k_zero_all(float* __restrict__ out) {
    int i = blockIdx.x * blockDim.x + threadIdx.x;
    if (i < NG * HID) out[i] = 0.f;
    if (i < NN) g_cnt[i] = 0;
}

// ---------------------------------------------------------------- CSR build
__global__ void k_hist(const int* __restrict__ ei) {
    int e = blockIdx.x * blockDim.x + threadIdx.x;
    if (e < EE) atomicAdd(&g_cnt[ei[EE + e]], 1);
}

__global__ __launch_bounds__(SCAN_CHUNK) void k_scan1() {
    __shared__ int s[SCAN_CHUNK];
    int tid = threadIdx.x;
    int i = blockIdx.x * SCAN_CHUNK + tid;
    int v = (i < NN) ? g_cnt[i] : 0;
    s[tid] = v;
    __syncthreads();
#pragma unroll
    for (int off = 1; off < SCAN_CHUNK; off <<= 1) {
        int t = (tid >= off) ? s[tid - off] : 0;
        __syncthreads();
        s[tid] += t;
        __syncthreads();
    }
    if (i < NN) g_scan[i] = s[tid];
    if (tid == SCAN_CHUNK - 1) g_bsum[blockIdx.x] = s[tid];
}

__global__ void k_scan3f() {
    __shared__ int boff[NCHUNK];
    if (threadIdx.x == 0) {
        int run = 0;
#pragma unroll 2
        for (int c = 0; c < NCHUNK; c++) { int t = g_bsum[c]; boff[c] = run; run += t; }
    }
    __syncthreads();
    int i = blockIdx.x * blockDim.x + threadIdx.x;
    if (i >= NN) return;
    int incl = g_scan[i] + boff[i / SCAN_CHUNK];
    g_rowptr[i + 1] = incl;
    g_cursor[i] = incl - g_cnt[i];
    if (i == 0) g_rowptr[0] = 0;
}

__global__ void k_reorder(const int* __restrict__ ei) {
    int e = blockIdx.x * blockDim.x + threadIdx.x;
    if (e >= EE) return;
    int d = ei[EE + e];
    int pos = atomicAdd(&g_cursor[d], 1);
    g_ss[pos] = ei[e];
}

// ---------------------------------------------------------------- aggregation
__global__ __launch_bounds__(256) void k_agg(const float* __restrict__ b) {
    int t = blockIdx.x * 256 + threadIdx.x;
    int n = t >> 4;
    int lane = t & 15;
    if (n >= NN) return;

    const float4* Y4 = (const float4*)g_Y;
    float4 bv = ((const float4*)b)[lane];
    float4 acc = Y4[(size_t)n * 16 + lane];
    acc.x += bv.x; acc.y += bv.y; acc.z += bv.z; acc.w += bv.w;

    int beg = g_rowptr[n], end = g_rowptr[n + 1];
#pragma unroll 4
    for (int e = beg; e < end; e++) {
        int s = g_ss[e];
        float4 v = Y4[(size_t)s * 16 + lane];
        acc.x += v.x; acc.y += v.y; acc.z += v.z; acc.w += v.w;
    }
    ((float4*)g_A)[(size_t)n * 16 + lane] = acc;
}

// ================================================================ in_proj via mma.sync (unchanged, round 9)
__global__ __launch_bounds__(256, 2) void k_in_proj_mma(
    const float* __restrict__ x, const float* __restrict__ W)
{
    extern __shared__ char smc[];
    uint32_t sb = smem_u32(smc);
    int tid = threadIdx.x;
    int w = tid >> 5, l = tid & 31;
    int m0 = blockIdx.x * 128;

    {
        int row = tid >> 1, half = tid & 1;
        int gm = m0 + row;
        bool ok = gm < NN;
        const float4* xr = (const float4*)(x + (size_t)gm * FIN + half * 64);
        int rbase = row * RSTRB + half * 128;
#pragma unroll
        for (int c = 0; c < 8; c++) {
            float4 f0 = ok ? xr[2 * c] : make_float4(0.f, 0.f, 0.f, 0.f);
            float4 f1 = ok ? xr[2 * c + 1] : make_float4(0.f, 0.f, 0.f, 0.f);
            float fv[8] = {f0.x, f0.y, f0.z, f0.w, f1.x, f1.y, f1.z, f1.w};
            uint32_t hp[4], lp[4];
            split8(fv, hp, lp);
            *(uint4*)(smc + XH_OFF + rbase + c * 16) = make_uint4(hp[0], hp[1], hp[2], hp[3]);
            *(uint4*)(smc + XL_OFF + rbase + c * 16) = make_uint4(lp[0], lp[1], lp[2], lp[3]);
        }
    }
    {
        int row = tid >> 2, q = tid & 3;
        const float4* wr = (const float4*)(W + (size_t)row * FIN + q * 32);
        int rbase = row * RSTRB + q * 64;
#pragma unroll
        for (int c = 0; c < 4; c++) {
            float4 f0 = wr[2 * c];
            float4 f1 = wr[2 * c + 1];
            float fv[8] = {f0.x, f0.y, f0.z, f0.w, f1.x, f1.y, f1.z, f1.w};
            uint32_t hp[4], lp[4];
            split8(fv, hp, lp);
            *(uint4*)(smc + WH_OFF + rbase + c * 16) = make_uint4(hp[0], hp[1], hp[2], hp[3]);
            *(uint4*)(smc + WL_OFF + rbase + c * 16) = make_uint4(lp[0], lp[1], lp[2], lp[3]);
        }
    }
    __syncthreads();

    uint32_t aAddr = sb + (uint32_t)((16 * w + (l & 15)) * RSTRB + (l >> 4) * 16);
    int bN = (l & 7) + ((l >> 4) << 3);
    int bKc = (l >> 3) & 1;
    uint32_t bAddr = sb + (uint32_t)(bN * RSTRB + bKc * 16);

    float D[8][4];
#pragma unroll
    for (int nc = 0; nc < 8; nc++)
#pragma unroll
        for (int j = 0; j < 4; j++) D[nc][j] = 0.f;

#pragma unroll
    for (int ks = 0; ks < 8; ks++) {
        uint32_t ko = ks * 32;
        uint32_t ah0, ah1, ah2, ah3, al0, al1, al2, al3;
        LDMX4(ah0, ah1, ah2, ah3, aAddr + XH_OFF + ko);
        LDMX4(al0, al1, al2, al3, aAddr + XL_OFF + ko);
#pragma unroll
        for (int g = 0; g < 4; g++) {
            uint32_t gb = bAddr + (uint32_t)(g * 16 * RSTRB) + ko;
            uint32_t bh0, bh1, bh2, bh3, bl0, bl1, bl2, bl3;
            LDMX4(bh0, bh1, bh2, bh3, gb + WH_OFF);
            LDMX4(bl0, bl1, bl2, bl3, gb + WL_OFF);
            MMA16816(D[2 * g],     ah0, ah1, ah2, ah3, bh0, bh1);
            MMA16816(D[2 * g],     ah0, ah1, ah2, ah3, bl0, bl1);
            MMA16816(D[2 * g],     al0, al1, al2, al3, bh0, bh1);
            MMA16816(D[2 * g + 1], ah0, ah1, ah2, ah3, bh2, bh3);
            MMA16816(D[2 * g + 1], ah0, ah1, ah2, ah3, bl2, bl3);
            MMA16816(D[2 * g + 1], al0, al1, al2, al3, bh2, bh3);
        }
    }

    int r0 = m0 + 16 * w + (l >> 2);
    int r1 = r0 + 8;
#pragma unroll
    for (int nc = 0; nc < 8; nc++) {
        int col = nc * 8 + (l & 3) * 2;
        if (r0 < NN) *(float2*)(g_Y + (size_t)r0 * HID + col) = make_float2(D[nc][0], D[nc][1]);
        if (r1 < NN) *(float2*)(g_Y + (size_t)r1 * HID + col) = make_float2(D[nc][2], D[nc][3]);
    }
}

// ================================================================ k_mid via mma.sync
// phase1: D1 = relu(A1) @ W1b^T; H = relu(bn1(D1)) re-packed to A-fragments in registers
// phase2: Y2 = H @ W2a^T -> g_Y. No SMEM round-trip for H.
__global__ __launch_bounds__(256, 2) void k_mid_mma(
    const float* __restrict__ W1b, const float* __restrict__ b1b,
    const float* __restrict__ g1,  const float* __restrict__ be1,
    const float* __restrict__ m1,  const float* __restrict__ v1,
    const float* __restrict__ W2a)
{
    extern __shared__ char smc[];
    uint32_t sb = smem_u32(smc);
    float* scp = (float*)(smc + MD_SC);
    float* shp = (float*)(smc + MD_SH);
    int tid = threadIdx.x;
    int w = tid >> 5, l = tid & 31;
    int m0 = blockIdx.x * 128;

    // stage A = relu(g_A) hi/lo: thread = (row, half)
    {
        int row = tid >> 1, half = tid & 1;
        int gm = m0 + row;
        bool ok = gm < NN;
        const float4* ar = (const float4*)(g_A + (size_t)gm * HID + half * 32);
        int rbase = row * RST2 + half * 64;
#pragma unroll
        for (int c = 0; c < 4; c++) {
            float4 f0 = ok ? ar[2 * c] : make_float4(0.f, 0.f, 0.f, 0.f);
            float4 f1 = ok ? ar[2 * c + 1] : make_float4(0.f, 0.f, 0.f, 0.f);
            float fv[8] = {fmaxf(f0.x, 0.f), fmaxf(f0.y, 0.f), fmaxf(f0.z, 0.f), fmaxf(f0.w, 0.f),
                           fmaxf(f1.x, 0.f), fmaxf(f1.y, 0.f), fmaxf(f1.z, 0.f), fmaxf(f1.w, 0.f)};
            uint32_t hp[4], lp[4];
            split8(fv, hp, lp);
            *(uint4*)(smc + MD_AH + rbase + c * 16) = make_uint4(hp[0], hp[1], hp[2], hp[3]);
            *(uint4*)(smc + MD_AL + rbase + c * 16) = make_uint4(lp[0], lp[1], lp[2], lp[3]);
        }
    }
    // stage W1b and W2a hi/lo: thread = (row, quarter) -> 16 k-values = 2 uint4 each
    // (round-10 bug: only 8 floats staged -> half of W uninitialized -> inf)
    {
        int row = tid >> 2, q = tid & 3;
        const float4* w1r = (const float4*)(W1b + (size_t)row * HID + q * 16);
        const float4* w2r = (const float4*)(W2a + (size_t)row * HID + q * 16);
#pragma unroll
        for (int c = 0; c < 2; c++) {
            int rb = row * RST2 + q * 32 + c * 16;
            float4 f0 = w1r[2 * c], f1 = w1r[2 * c + 1];
            float fv[8] = {f0.x, f0.y, f0.z, f0.w, f1.x, f1.y, f1.z, f1.w};
            uint32_t hp[4], lp[4];
            split8(fv, hp, lp);
            *(uint4*)(smc + MD_W1H + rb) = make_uint4(hp[0], hp[1], hp[2], hp[3]);
            *(uint4*)(smc + MD_W1L + rb) = make_uint4(lp[0], lp[1], lp[2], lp[3]);
            f0 = w2r[2 * c]; f1 = w2r[2 * c + 1];
            float gv[8] = {f0.x, f0.y, f0.z, f0.w, f1.x, f1.y, f1.z, f1.w};
            split8(gv, hp, lp);
            *(uint4*)(smc + MD_W2H + rb) = make_uint4(hp[0], hp[1], hp[2], hp[3]);
            *(uint4*)(smc + MD_W2L + rb) = make_uint4(lp[0], lp[1], lp[2], lp[3]);
        }
    }
    if (tid < HID) {
        float s = g1[tid] * rsqrtf(v1[tid] + BN_EPS_F);
        scp[tid] = s;
        shp[tid] = (b1b[tid] - m1[tid]) * s + be1[tid];
    }
    __syncthreads();

    uint32_t aAddr = sb + (uint32_t)((16 * w + (l & 15)) * RST2 + (l >> 4) * 16);
    int bN = (l & 7) + ((l >> 4) << 3);
    int bKc = (l >> 3) & 1;
    uint32_t bAddr = sb + (uint32_t)(bN * RST2 + bKc * 16);

    float D[8][4];
#pragma unroll
    for (int nc = 0; nc < 8; nc++)
#pragma unroll
        for (int j = 0; j < 4; j++) D[nc][j] = 0.f;

    // ---- phase 1 (k = 64 -> 4 k-steps)
#pragma unroll
    for (int ks = 0; ks < 4; ks++) {
        uint32_t ko = ks * 32;
        uint32_t ah0, ah1, ah2, ah3, al0, al1, al2, al3;
        LDMX4(ah0, ah1, ah2, ah3, aAddr + MD_AH + ko);
        LDMX4(al0, al1, al2, al3, aAddr + MD_AL + ko);
#pragma unroll
        for (int g = 0; g < 4; g++) {
            uint32_t gb = bAddr + (uint32_t)(g * 16 * RST2) + ko;
            uint32_t bh0, bh1, bh2, bh3, bl0, bl1, bl2, bl3;
            LDMX4(bh0, bh1, bh2, bh3, gb + MD_W1H);
            LDMX4(bl0, bl1, bl2, bl3, gb + MD_W1L);
            MMA16816(D[2 * g],     ah0, ah1, ah2, ah3, bh0, bh1);
            MMA16816(D[2 * g],     ah0, ah1, ah2, ah3, bl0, bl1);
            MMA16816(D[2 * g],     al0, al1, al2, al3, bh0, bh1);
            MMA16816(D[2 * g + 1], ah0, ah1, ah2, ah3, bh2, bh3);
            MMA16816(D[2 * g + 1], ah0, ah1, ah2, ah3, bl2, bl3);
            MMA16816(D[2 * g + 1], al0, al1, al2, al3, bh2, bh3);
        }
    }

    // ---- bn1 + relu in registers, re-pack D -> phase-2 A fragments
    uint32_t ahi[4][4], alo[4][4];
    {
        int t2 = (l & 3) * 2;
#pragma unroll
        for (int nc = 0; nc < 8; nc++) {
            int col = nc * 8 + t2;
            float s0 = scp[col], s1 = scp[col + 1];
            float t0 = shp[col], t1 = shp[col + 1];
            D[nc][0] = fmaxf(fmaf(D[nc][0], s0, t0), 0.f);
            D[nc][1] = fmaxf(fmaf(D[nc][1], s1, t1), 0.f);
            D[nc][2] = fmaxf(fmaf(D[nc][2], s0, t0), 0.f);
            D[nc][3] = fmaxf(fmaf(D[nc][3], s1, t1), 0.f);
        }
#pragma unroll
        for (int kc = 0; kc < 4; kc++) {
#pragma unroll
            for (int j = 0; j < 4; j++) {
                float h0 = D[2 * kc + (j >> 1)][(j & 1) * 2 + 0];
                float h1 = D[2 * kc + (j >> 1)][(j & 1) * 2 + 1];
                uint32_t hp;
                BF2(hp, h0, h1);
                float l0 = h0 - __uint_as_float(hp << 16);
                float l1 = h1 - __uint_as_float(hp & 0xFFFF0000u);
                uint32_t lp;
                BF2(lp, l0, l1);
                ahi[kc][j] = hp;   // j: 0=a0(row g,k-lo) 1=a1(row g+8,k-lo) 2=a2(row g,k-hi) 3=a3
                alo[kc][j] = lp;
            }
        }
    }

    // ---- phase 2
    float D2[8][4];
#pragma unroll
    for (int nc = 0; nc < 8; nc++)
#pragma unroll
        for (int j = 0; j < 4; j++) D2[nc][j] = 0.f;

#pragma unroll
    for (int kc = 0; kc < 4; kc++) {
        uint32_t ko = kc * 32;
#pragma unroll
        for (int g = 0; g < 4; g++) {
            uint32_t gb = bAddr + (uint32_t)(g * 16 * RST2) + ko;
            uint32_t bh0, bh1, bh2, bh3, bl0, bl1, bl2, bl3;
            LDMX4(bh0, bh1, bh2, bh3, gb + MD_W2H);
            LDMX4(bl0, bl1, bl2, bl3, gb + MD_W2L);
            MMA16816(D2[2 * g],     ahi[kc][0], ahi[kc][1], ahi[kc][2], ahi[kc][3], bh0, bh1);
            MMA16816(D2[2 * g],     ahi[kc][0], ahi[kc][1], ahi[kc][2], ahi[kc][3], bl0, bl1);
            MMA16816(D2[2 * g],     alo[kc][0], alo[kc][1], alo[kc][2], alo[kc][3], bh0, bh1);
            MMA16816(D2[2 * g + 1], ahi[kc][0], ahi[kc][1], ahi[kc][2], ahi[kc][3], bh2, bh3);
            MMA16816(D2[2 * g + 1], ahi[kc][0], ahi[kc][1], ahi[kc][2], ahi[kc][3], bl2, bl3);
            MMA16816(D2[2 * g + 1], alo[kc][0], alo[kc][1], alo[kc][2], alo[kc][3], bh2, bh3);
        }
    }

    int r0 = m0 + 16 * w + (l >> 2);
    int r1 = r0 + 8;
#pragma unroll
    for (int nc = 0; nc < 8; nc++) {
        int col = nc * 8 + (l & 3) * 2;
        if (r0 < NN) *(float2*)(g_Y + (size_t)r0 * HID + col) = make_float2(D2[nc][0], D2[nc][1]);
        if (r1 < NN) *(float2*)(g_Y + (size_t)r1 * HID + col) = make_float2(D2[nc][2], D2[nc][3]);
    }
}

// ================================================================ k_final via mma.sync
// D = relu(A2) @ W2b^T; out[batch[n]] += relu(bn2(D))
__global__ __launch_bounds__(256, 2) void k_final_mma(
    const float* __restrict__ W2b, const float* __restrict__ bb,
    const float* __restrict__ ga,  const float* __restrict__ be,
    const float* __restrict__ mm,  const float* __restrict__ vv,
    const int* __restrict__ batch, float* __restrict__ out)
{
    extern __shared__ char smc[];
    uint32_t sb = smem_u32(smc);
    float* scp = (float*)(smc + FN_SC);
    float* shp = (float*)(smc + FN_SH);
    int tid = threadIdx.x;
    int w = tid >> 5, l = tid & 31;
    int m0 = blockIdx.x * 128;

    {
        int row = tid >> 1, half = tid & 1;
        int gm = m0 + row;
        bool ok = gm < NN;
        const float4* ar = (const float4*)(g_A + (size_t)gm * HID + half * 32);
        int rbase = row * RST2 + half * 64;
#pragma unroll
        for (int c = 0; c < 4; c++) {
            float4 f0 = ok ? ar[2 * c] : make_float4(0.f, 0.f, 0.f, 0.f);
            float4 f1 = ok ? ar[2 * c + 1] : make_float4(0.f, 0.f, 0.f, 0.f);
            float fv[8] = {fmaxf(f0.x, 0.f), fmaxf(f0.y, 0.f), fmaxf(f0.z, 0.f), fmaxf(f0.w, 0.f),
                           fmaxf(f1.x, 0.f), fmaxf(f1.y, 0.f), fmaxf(f1.z, 0.f), fmaxf(f1.w, 0.f)};
            uint32_t hp[4], lp[4];
            split8(fv, hp, lp);
            *(uint4*)(smc + FN_AH + rbase + c * 16) = make_uint4(hp[0], hp[1], hp[2], hp[3]);
            *(uint4*)(smc + FN_AL + rbase + c * 16) = make_uint4(lp[0], lp[1], lp[2], lp[3]);
        }
    }
    // W2b staging: 16 floats per (row, q) = 2 uint4  (round-10 bug fixed)
    {
        int row = tid >> 2, q = tid & 3;
        const float4* wr = (const float4*)(W2b + (size_t)row * HID + q * 16);
#pragma unroll
        for (int c = 0; c < 2; c++) {
            int rb = row * RST2 + q * 32 + c * 16;
            float4 f0 = wr[2 * c], f1 = wr[2 * c + 1];
            float fv[8] = {f0.x, f0.y, f0.z, f0.w, f1.x, f1.y, f1.z, f1.w};
            uint32_t hp[4], lp[4];
            split8(fv, hp, lp);
            *(uint4*)(smc + FN_WH + rb) = make_uint4(hp[0], hp[1], hp[2], hp[3]);
            *(uint4*)(smc + FN_WL + rb) = make_uint4(lp[0], lp[1], lp[2], lp[3]);
        }
    }
    if (tid < HID) {
        float s = ga[tid] * rsqrtf(vv[tid] + BN_EPS_F);
        scp[tid] = s;
        shp[tid] = (bb[tid] - mm[tid]) * s + be[tid];
    }
    __syncthreads();

    uint32_t aAddr = sb + (uint32_t)((16 * w + (l & 15)) * RST2 + (l >> 4) * 16);
    int bN = (l & 7) + ((l >> 4) << 3);
    int bKc = (l >> 3) & 1;
    uint32_t bAddr = sb + (uint32_t)(bN * RST2 + bKc * 16);

    float D[8][4];
#pragma unroll
    for (int nc = 0; nc < 8; nc++)
#pragma unroll
        for (int j = 0; j < 4; j++) D[nc][j] = 0.f;

#pragma unroll
    for (int ks = 0; ks < 4; ks++) {
        uint32_t ko = ks * 32;
        uint32_t ah0, ah1, ah2, ah3, al0, al1, al2, al3;
        LDMX4(ah0, ah1, ah2, ah3, aAddr + FN_AH + ko);
        LDMX4(al0, al1, al2, al3, aAddr + FN_AL + ko);
#pragma unroll
        for (int g = 0; g < 4; g++) {
            uint32_t gb = bAddr + (uint32_t)(g * 16 * RST2) + ko;
            uint32_t bh0, bh1, bh2, bh3, bl0, bl1, bl2, bl3;
            LDMX4(bh0, bh1, bh2, bh3, gb + FN_WH);
            LDMX4(bl0, bl1, bl2, bl3, gb + FN_WL);
            MMA16816(D[2 * g],     ah0, ah1, ah2, ah3, bh0, bh1);
            MMA16816(D[2 * g],     ah0, ah1, ah2, ah3, bl0, bl1);
            MMA16816(D[2 * g],     al0, al1, al2, al3, bh0, bh1);
            MMA16816(D[2 * g + 1], ah0, ah1, ah2, ah3, bh2, bh3);
            MMA16816(D[2 * g + 1], ah0, ah1, ah2, ah3, bl2, bl3);
            MMA16816(D[2 * g + 1], al0, al1, al2, al3, bh2, bh3);
        }
    }

    // epilogue: bn2 + relu, pool via red.v2
    int r0 = m0 + 16 * w + (l >> 2);
    int r1 = r0 + 8;
    int gb0 = (r0 < NN) ? batch[r0] : 0;
    int gb1 = (r1 < NN) ? batch[r1] : 0;
    int t2 = (l & 3) * 2;
#pragma unroll
    for (int nc = 0; nc < 8; nc++) {
        int col = nc * 8 + t2;
        float s0 = scp[col], s1 = scp[col + 1];
        float t0 = shp[col], t1 = shp[col + 1];
        if (r0 < NN)
            red_add_v2(out + (size_t)gb0 * HID + col,
                       fmaxf(fmaf(D[nc][0], s0, t0), 0.f),
                       fmaxf(fmaf(D[nc][1], s1, t1), 0.f));
        if (r1 < NN)
            red_add_v2(out + (size_t)gb1 * HID + col,
                       fmaxf(fmaf(D[nc][2], s0, t0), 0.f),
                       fmaxf(fmaf(D[nc][3], s1, t1), 0.f));
    }
}

// ------------------------------------------------- divide by per-graph counts
__global__ void k_div(const int* __restrict__ batch, float* __restrict__ out)
{
    int g = blockIdx.x;
    __shared__ int cnt;
    if (threadIdx.x == 0) {
        int lo = 0, hi = NN;
        while (lo < hi) { int mid = (lo + hi) >> 1; if (batch[mid] < g) lo = mid + 1; else hi = mid; }
        int lo2 = lo, hi2 = NN;
        while (lo2 < hi2) { int mid = (lo2 + hi2) >> 1; if (batch[mid] < g + 1) lo2 = mid + 1; else hi2 = mid; }
        cnt = lo2 - lo;
    }
    __syncthreads();
    float c = (float)(cnt > 1 ? cnt : 1);
    out[(size_t)g * HID + threadIdx.x] /= c;
}

// ---------------------------------------------------------------- launch
extern "C" void kernel_launch(void* const* d_in, const int* in_sizes, int n_in,
                              void* d_out, int out_size)
{
    (void)in_sizes; (void)n_in; (void)out_size;
    const float* x    = (const float*)d_in[0];
    const int*   ei   = (const int*)d_in[1];
    const int*   batch= (const int*)d_in[2];
    const float* W1a  = (const float*)d_in[3];
    const float* b1a  = (const float*)d_in[4];
    const float* W1b  = (const float*)d_in[5];
    const float* b1b  = (const float*)d_in[6];
    const float* g1   = (const float*)d_in[7];
    const float* be1  = (const float*)d_in[8];
    const float* m1   = (const float*)d_in[9];
    const float* v1   = (const float*)d_in[10];
    const float* W2a  = (const float*)d_in[11];
    const float* b2a  = (const float*)d_in[12];
    const float* W2b  = (const float*)d_in[13];
    const float* b2b  = (const float*)d_in[14];
    const float* g2   = (const float*)d_in[15];
    const float* be2  = (const float*)d_in[16];
    const float* m2   = (const float*)d_in[17];
    const float* v2   = (const float*)d_in[18];
    float* out = (float*)d_out;

    cudaFuncSetAttribute(k_in_proj_mma, cudaFuncAttributeMaxDynamicSharedMemorySize, MMA_SMEM);
    cudaFuncSetAttribute(k_mid_mma,     cudaFuncAttributeMaxDynamicSharedMemorySize, MD_SMEM);
    cudaFuncSetAttribute(k_final_mma,   cudaFuncAttributeMaxDynamicSharedMemorySize, FN_SMEM);

    int gemmBlocks = (NN + 127) / 128;             // 782
    int edgeBlocks = (EE + 255) / 256;             // 6250
    int aggBlocks  = (NN * 16 + 255) / 256;        // 6250

    k_zero_all<<<(NN + 255) / 256, 256>>>(out);
    k_hist<<<edgeBlocks, 256>>>(ei);
    k_scan1<<<NCHUNK, SCAN_CHUNK>>>();
    // slot 4 (profiled): mma.sync in_proj — dependency-free w.r.t. CSR chain
    k_in_proj_mma<<<gemmBlocks, 256, MMA_SMEM>>>(x, W1a);
    k_scan3f<<<(NN + 255) / 256, 256>>>();
    k_reorder<<<edgeBlocks, 256>>>(ei);

    // layer 1 + mid
    k_agg<<<aggBlocks, 256>>>(b1a);
    k_mid_mma<<<gemmBlocks, 256, MD_SMEM>>>(W1b, b1b, g1, be1, m1, v1, W2a);

    // layer 2
    k_agg<<<aggBlocks, 256>>>(b2a);
    k_final_mma<<<gemmBlocks, 256, FN_SMEM>>>(W2b, b2b, g2, be2, m2, v2, batch, out);
    k_div<<<NG, HID>>>(batch, out);
}

// round 12
// speedup vs baseline: 1.5017x; 1.0387x over previous
#include <cuda_runtime.h>
#include <cuda_bf16.h>
#include <cstdint>

#define NN 100000
#define EE 1600000
#define FIN 128
#define HID 64
#define NG 512
#define BN_EPS_F 1e-5f

#define SCAN_CHUNK 1024
#define NCHUNK ((NN + SCAN_CHUNK - 1) / SCAN_CHUNK)   // 98

// mma.sync in_proj tile: SMEM bf16 rows padded (K=128 -> 136 elems = 272B)
#define RSTRB 272
#define XH_OFF 0
#define XL_OFF 34816
#define WH_OFF 69632
#define WL_OFF 87040
#define MMA_SMEM 104448

// K=64 mma tiles (mid / final): bf16 rows padded to 72 elems = 144B
#define RST2 144
// k_mid smem layout (bytes)
#define MD_AH 0
#define MD_AL 18432
#define MD_W1H 36864
#define MD_W1L 46080
#define MD_W2H 55296
#define MD_W2L 64512
#define MD_SC 73728
#define MD_SH 73984
#define MD_SMEM 74240
// k_final smem layout
#define FN_AH 0
#define FN_AL 18432
#define FN_WH 36864
#define FN_WL 46080
#define FN_SC 55296
#define FN_SH 55552
#define FN_SMEM 55808

typedef unsigned long long ull;

// Scratch (allocation-free rule: __device__ globals).
__device__ __align__(16) float g_Y[(size_t)NN * HID];
__device__ __align__(16) float g_A[(size_t)NN * HID];
__device__ int g_cnt[NN];
__device__ int g_scan[NN];
__device__ int g_bsum[NCHUNK];
__device__ int g_rowptr[NN + 1];
__device__ int g_cursor[NN];
__device__ int g_ss[EE];

__device__ __forceinline__ void red_add_v2(float* p, float a, float b) {
    asm volatile("red.global.add.v2.f32 [%0], {%1,%2};"
                 :: "l"(p), "f"(a), "f"(b) : "memory");
}

__device__ __forceinline__ uint32_t smem_u32(const void* p) {
    uint32_t a;
    asm("{ .reg .u64 t; cvta.to.shared.u64 t, %1; cvt.u32.u64 %0, t; }" : "=r"(a) : "l"(p));
    return a;
}
// pack two floats -> bf16x2 (first arg -> low 16 bits)
#define BF2(res, a, b) asm("cvt.rn.satfinite.bf16x2.f32 %0, %1, %2;" : "=r"(res) : "f"(b), "f"(a))

#define LDMX4(r0, r1, r2, r3, addr)                                             \
    asm volatile("ldmatrix.sync.aligned.m8n8.x4.shared.b16 {%0,%1,%2,%3}, [%4];" \
                 : "=r"(r0), "=r"(r1), "=r"(r2), "=r"(r3) : "r"(addr))

#define MMA16816(d, a0, a1, a2, a3, b0, b1)                                     \
    asm volatile("mma.sync.aligned.m16n8k16.row.col.f32.bf16.bf16.f32 "         \
                 "{%0,%1,%2,%3}, {%4,%5,%6,%7}, {%8,%9}, {%0,%1,%2,%3};"        \
                 : "+f"((d)[0]), "+f"((d)[1]), "+f"((d)[2]), "+f"((d)[3])       \
                 : "r"(a0), "r"(a1), "r"(a2), "r"(a3), "r"(b0), "r"(b1))

// split 8 floats into bf16x2 hi/lo quads
__device__ __forceinline__ void split8(const float* fv, uint32_t* hp, uint32_t* lp) {
#pragma unroll
    for (int j = 0; j < 4; j++) {
        BF2(hp[j], fv[2 * j], fv[2 * j + 1]);
        float l0 = fv[2 * j]     - __uint_as_float(hp[j] << 16);
        float l1 = fv[2 * j + 1] - __uint_as_float(hp[j] & 0xFFFF0000u);
        BF2(lp[j], l0, l1);
    }
}

// ---------------------------------------------------------------- fused zero
__global__ void k_zero_all(float* __restrict__ out) {
    int i = blockIdx.x * blockDim.x + threadIdx.x;
    if (i < NG * HID) out[i] = 0.f;
    if (i < NN) g_cnt[i] = 0;
}

// ---------------------------------------------------------------- CSR build
__global__ void k_hist(const int* __restrict__ ei) {
    int e = blockIdx.x * blockDim.x + threadIdx.x;
    if (e < EE) atomicAdd(&g_cnt[ei[EE + e]], 1);
}

__global__ __launch_bounds__(SCAN_CHUNK) void k_scan1() {
    __shared__ int s[SCAN_CHUNK];
    int tid = threadIdx.x;
    int i = blockIdx.x * SCAN_CHUNK + tid;
    int v = (i < NN) ? g_cnt[i] : 0;
    s[tid] = v;
    __syncthreads();
#pragma unroll
    for (int off = 1; off < SCAN_CHUNK; off <<= 1) {
        int t = (tid >= off) ? s[tid - off] : 0;
        __syncthreads();
        s[tid] += t;
        __syncthreads();
    }
    if (i < NN) g_scan[i] = s[tid];
    if (tid == SCAN_CHUNK - 1) g_bsum[blockIdx.x] = s[tid];
}

__global__ void k_scan3f() {
    __shared__ int boff[NCHUNK];
    if (threadIdx.x == 0) {
        int run = 0;
#pragma unroll 2
        for (int c = 0; c < NCHUNK; c++) { int t = g_bsum[c]; boff[c] = run; run += t; }
    }
    __syncthreads();
    int i = blockIdx.x * blockDim.x + threadIdx.x;
    if (i >= NN) return;
    int incl = g_scan[i] + boff[i / SCAN_CHUNK];
    g_rowptr[i + 1] = incl;
    g_cursor[i] = incl - g_cnt[i];
    if (i == 0) g_rowptr[0] = 0;
}

__global__ void k_reorder(const int* __restrict__ ei) {
    int e = blockIdx.x * blockDim.x + threadIdx.x;
    if (e >= EE) return;
    int d = ei[EE + e];
    int pos = atomicAdd(&g_cursor[d], 1);
    g_ss[pos] = ei[e];
}

// ---------------------------------------------------------------- aggregation
__global__ __launch_bounds__(256) void k_agg(const float* __restrict__ b) {
    int t = blockIdx.x * 256 + threadIdx.x;
    int n = t >> 4;
    int lane = t & 15;
    if (n >= NN) return;

    const float4* Y4 = (const float4*)g_Y;
    float4 bv = ((const float4*)b)[lane];
    float4 acc = Y4[(size_t)n * 16 + lane];
    acc.x += bv.x; acc.y += bv.y; acc.z += bv.z; acc.w += bv.w;

    int beg = g_rowptr[n], end = g_rowptr[n + 1];
#pragma unroll 4
    for (int e = beg; e < end; e++) {
        int s = g_ss[e];
        float4 v = Y4[(size_t)s * 16 + lane];
        acc.x += v.x; acc.y += v.y; acc.z += v.z; acc.w += v.w;
    }
    ((float4*)g_A)[(size_t)n * 16 + lane] = acc;
}

// ================================================================ in_proj via mma.sync
__global__ __launch_bounds__(256, 2) void k_in_proj_mma(
    const float* __restrict__ x, const float* __restrict__ W)
{
    extern __shared__ char smc[];
    uint32_t sb = smem_u32(smc);
    int tid = threadIdx.x;
    int w = tid >> 5, l = tid & 31;
    int m0 = blockIdx.x * 128;

    {
        int row = tid >> 1, half = tid & 1;
        int gm = m0 + row;
        bool ok = gm < NN;
        const float4* xr = (const float4*)(x + (size_t)gm * FIN + half * 64);
        int rbase = row * RSTRB + half * 128;
#pragma unroll
        for (int c = 0; c < 8; c++) {
            float4 f0 = ok ? xr[2 * c] : make_float4(0.f, 0.f, 0.f, 0.f);
            float4 f1 = ok ? xr[2 * c + 1] : make_float4(0.f, 0.f, 0.f, 0.f);
            float fv[8] = {f0.x, f0.y, f0.z, f0.w, f1.x, f1.y, f1.z, f1.w};
            uint32_t hp[4], lp[4];
            split8(fv, hp, lp);
            *(uint4*)(smc + XH_OFF + rbase + c * 16) = make_uint4(hp[0], hp[1], hp[2], hp[3]);
            *(uint4*)(smc + XL_OFF + rbase + c * 16) = make_uint4(lp[0], lp[1], lp[2], lp[3]);
        }
    }
    {
        int row = tid >> 2, q = tid & 3;
        const float4* wr = (const float4*)(W + (size_t)row * FIN + q * 32);
        int rbase = row * RSTRB + q * 64;
#pragma unroll
        for (int c = 0; c < 4; c++) {
            float4 f0 = wr[2 * c];
            float4 f1 = wr[2 * c + 1];
            float fv[8] = {f0.x, f0.y, f0.z, f0.w, f1.x, f1.y, f1.z, f1.w};
            uint32_t hp[4], lp[4];
            split8(fv, hp, lp);
            *(uint4*)(smc + WH_OFF + rbase + c * 16) = make_uint4(hp[0], hp[1], hp[2], hp[3]);
            *(uint4*)(smc + WL_OFF + rbase + c * 16) = make_uint4(lp[0], lp[1], lp[2], lp[3]);
        }
    }
    __syncthreads();

    uint32_t aAddr = sb + (uint32_t)((16 * w + (l & 15)) * RSTRB + (l >> 4) * 16);
    int bN = (l & 7) + ((l >> 4) << 3);
    int bKc = (l >> 3) & 1;
    uint32_t bAddr = sb + (uint32_t)(bN * RSTRB + bKc * 16);

    float D[8][4];
#pragma unroll
    for (int nc = 0; nc < 8; nc++)
#pragma unroll
        for (int j = 0; j < 4; j++) D[nc][j] = 0.f;

#pragma unroll
    for (int ks = 0; ks < 8; ks++) {
        uint32_t ko = ks * 32;
        uint32_t ah0, ah1, ah2, ah3, al0, al1, al2, al3;
        LDMX4(ah0, ah1, ah2, ah3, aAddr + XH_OFF + ko);
        LDMX4(al0, al1, al2, al3, aAddr + XL_OFF + ko);
#pragma unroll
        for (int g = 0; g < 4; g++) {
            uint32_t gb = bAddr + (uint32_t)(g * 16 * RSTRB) + ko;
            uint32_t bh0, bh1, bh2, bh3, bl0, bl1, bl2, bl3;
            LDMX4(bh0, bh1, bh2, bh3, gb + WH_OFF);
            LDMX4(bl0, bl1, bl2, bl3, gb + WL_OFF);
            MMA16816(D[2 * g],     ah0, ah1, ah2, ah3, bh0, bh1);
            MMA16816(D[2 * g],     ah0, ah1, ah2, ah3, bl0, bl1);
            MMA16816(D[2 * g],     al0, al1, al2, al3, bh0, bh1);
            MMA16816(D[2 * g + 1], ah0, ah1, ah2, ah3, bh2, bh3);
            MMA16816(D[2 * g + 1], ah0, ah1, ah2, ah3, bl2, bl3);
            MMA16816(D[2 * g + 1], al0, al1, al2, al3, bh2, bh3);
        }
    }

    int r0 = m0 + 16 * w + (l >> 2);
    int r1 = r0 + 8;
#pragma unroll
    for (int nc = 0; nc < 8; nc++) {
        int col = nc * 8 + (l & 3) * 2;
        if (r0 < NN) *(float2*)(g_Y + (size_t)r0 * HID + col) = make_float2(D[nc][0], D[nc][1]);
        if (r1 < NN) *(float2*)(g_Y + (size_t)r1 * HID + col) = make_float2(D[nc][2], D[nc][3]);
    }
}

// ================================================================ k_mid via mma.sync
__global__ __launch_bounds__(256, 2) void k_mid_mma(
    const float* __restrict__ W1b, const float* __restrict__ b1b,
    const float* __restrict__ g1,  const float* __restrict__ be1,
    const float* __restrict__ m1,  const float* __restrict__ v1,
    const float* __restrict__ W2a)
{
    extern __shared__ char smc[];
    uint32_t sb = smem_u32(smc);
    float* scp = (float*)(smc + MD_SC);
    float* shp = (float*)(smc + MD_SH);
    int tid = threadIdx.x;
    int w = tid >> 5, l = tid & 31;
    int m0 = blockIdx.x * 128;

    {
        int row = tid >> 1, half = tid & 1;
        int gm = m0 + row;
        bool ok = gm < NN;
        const float4* ar = (const float4*)(g_A + (size_t)gm * HID + half * 32);
        int rbase = row * RST2 + half * 64;
#pragma unroll
        for (int c = 0; c < 4; c++) {
            float4 f0 = ok ? ar[2 * c] : make_float4(0.f, 0.f, 0.f, 0.f);
            float4 f1 = ok ? ar[2 * c + 1] : make_float4(0.f, 0.f, 0.f, 0.f);
            float fv[8] = {fmaxf(f0.x, 0.f), fmaxf(f0.y, 0.f), fmaxf(f0.z, 0.f), fmaxf(f0.w, 0.f),
                           fmaxf(f1.x, 0.f), fmaxf(f1.y, 0.f), fmaxf(f1.z, 0.f), fmaxf(f1.w, 0.f)};
            uint32_t hp[4], lp[4];
            split8(fv, hp, lp);
            *(uint4*)(smc + MD_AH + rbase + c * 16) = make_uint4(hp[0], hp[1], hp[2], hp[3]);
            *(uint4*)(smc + MD_AL + rbase + c * 16) = make_uint4(lp[0], lp[1], lp[2], lp[3]);
        }
    }
    {
        int row = tid >> 2, q = tid & 3;
        const float4* w1r = (const float4*)(W1b + (size_t)row * HID + q * 16);
        const float4* w2r = (const float4*)(W2a + (size_t)row * HID + q * 16);
#pragma unroll
        for (int c = 0; c < 2; c++) {
            int rb = row * RST2 + q * 32 + c * 16;
            float4 f0 = w1r[2 * c], f1 = w1r[2 * c + 1];
            float fv[8] = {f0.x, f0.y, f0.z, f0.w, f1.x, f1.y, f1.z, f1.w};
            uint32_t hp[4], lp[4];
            split8(fv, hp, lp);
            *(uint4*)(smc + MD_W1H + rb) = make_uint4(hp[0], hp[1], hp[2], hp[3]);
            *(uint4*)(smc + MD_W1L + rb) = make_uint4(lp[0], lp[1], lp[2], lp[3]);
            f0 = w2r[2 * c]; f1 = w2r[2 * c + 1];
            float gv[8] = {f0.x, f0.y, f0.z, f0.w, f1.x, f1.y, f1.z, f1.w};
            split8(gv, hp, lp);
            *(uint4*)(smc + MD_W2H + rb) = make_uint4(hp[0], hp[1], hp[2], hp[3]);
            *(uint4*)(smc + MD_W2L + rb) = make_uint4(lp[0], lp[1], lp[2], lp[3]);
        }
    }
    if (tid < HID) {
        float s = g1[tid] * rsqrtf(v1[tid] + BN_EPS_F);
        scp[tid] = s;
        shp[tid] = (b1b[tid] - m1[tid]) * s + be1[tid];
    }
    __syncthreads();

    uint32_t aAddr = sb + (uint32_t)((16 * w + (l & 15)) * RST2 + (l >> 4) * 16);
    int bN = (l & 7) + ((l >> 4) << 3);
    int bKc = (l >> 3) & 1;
    uint32_t bAddr = sb + (uint32_t)(bN * RST2 + bKc * 16);

    float D[8][4];
#pragma unroll
    for (int nc = 0; nc < 8; nc++)
#pragma unroll
        for (int j = 0; j < 4; j++) D[nc][j] = 0.f;

#pragma unroll
    for (int ks = 0; ks < 4; ks++) {
        uint32_t ko = ks * 32;
        uint32_t ah0, ah1, ah2, ah3, al0, al1, al2, al3;
        LDMX4(ah0, ah1, ah2, ah3, aAddr + MD_AH + ko);
        LDMX4(al0, al1, al2, al3, aAddr + MD_AL + ko);
#pragma unroll
        for (int g = 0; g < 4; g++) {
            uint32_t gb = bAddr + (uint32_t)(g * 16 * RST2) + ko;
            uint32_t bh0, bh1, bh2, bh3, bl0, bl1, bl2, bl3;
            LDMX4(bh0, bh1, bh2, bh3, gb + MD_W1H);
            LDMX4(bl0, bl1, bl2, bl3, gb + MD_W1L);
            MMA16816(D[2 * g],     ah0, ah1, ah2, ah3, bh0, bh1);
            MMA16816(D[2 * g],     ah0, ah1, ah2, ah3, bl0, bl1);
            MMA16816(D[2 * g],     al0, al1, al2, al3, bh0, bh1);
            MMA16816(D[2 * g + 1], ah0, ah1, ah2, ah3, bh2, bh3);
            MMA16816(D[2 * g + 1], ah0, ah1, ah2, ah3, bl2, bl3);
            MMA16816(D[2 * g + 1], al0, al1, al2, al3, bh2, bh3);
        }
    }

    uint32_t ahi[4][4], alo[4][4];
    {
        int t2 = (l & 3) * 2;
#pragma unroll
        for (int nc = 0; nc < 8; nc++) {
            int col = nc * 8 + t2;
            float s0 = scp[col], s1 = scp[col + 1];
            float t0 = shp[col], t1 = shp[col + 1];
            D[nc][0] = fmaxf(fmaf(D[nc][0], s0, t0), 0.f);
            D[nc][1] = fmaxf(fmaf(D[nc][1], s1, t1), 0.f);
            D[nc][2] = fmaxf(fmaf(D[nc][2], s0, t0), 0.f);
            D[nc][3] = fmaxf(fmaf(D[nc][3], s1, t1), 0.f);
        }
#pragma unroll
        for (int kc = 0; kc < 4; kc++) {
#pragma unroll
            for (int j = 0; j < 4; j++) {
                float h0 = D[2 * kc + (j >> 1)][(j & 1) * 2 + 0];
                float h1 = D[2 * kc + (j >> 1)][(j & 1) * 2 + 1];
                uint32_t hp;
                BF2(hp, h0, h1);
                float l0 = h0 - __uint_as_float(hp << 16);
                float l1 = h1 - __uint_as_float(hp & 0xFFFF0000u);
                uint32_t lp;
                BF2(lp, l0, l1);
                ahi[kc][j] = hp;
                alo[kc][j] = lp;
            }
        }
    }

    float D2[8][4];
#pragma unroll
    for (int nc = 0; nc < 8; nc++)
#pragma unroll
        for (int j = 0; j < 4; j++) D2[nc][j] = 0.f;

#pragma unroll
    for (int kc = 0; kc < 4; kc++) {
        uint32_t ko = kc * 32;
#pragma unroll
        for (int g = 0; g < 4; g++) {
            uint32_t gb = bAddr + (uint32_t)(g * 16 * RST2) + ko;
            uint32_t bh0, bh1, bh2, bh3, bl0, bl1, bl2, bl3;
            LDMX4(bh0, bh1, bh2, bh3, gb + MD_W2H);
            LDMX4(bl0, bl1, bl2, bl3, gb + MD_W2L);
            MMA16816(D2[2 * g],     ahi[kc][0], ahi[kc][1], ahi[kc][2], ahi[kc][3], bh0, bh1);
            MMA16816(D2[2 * g],     ahi[kc][0], ahi[kc][1], ahi[kc][2], ahi[kc][3], bl0, bl1);
            MMA16816(D2[2 * g],     alo[kc][0], alo[kc][1], alo[kc][2], alo[kc][3], bh0, bh1);
            MMA16816(D2[2 * g + 1], ahi[kc][0], ahi[kc][1], ahi[kc][2], ahi[kc][3], bh2, bh3);
            MMA16816(D2[2 * g + 1], ahi[kc][0], ahi[kc][1], ahi[kc][2], ahi[kc][3], bl2, bl3);
            MMA16816(D2[2 * g + 1], alo[kc][0], alo[kc][1], alo[kc][2], alo[kc][3], bh2, bh3);
        }
    }

    int r0 = m0 + 16 * w + (l >> 2);
    int r1 = r0 + 8;
#pragma unroll
    for (int nc = 0; nc < 8; nc++) {
        int col = nc * 8 + (l & 3) * 2;
        if (r0 < NN) *(float2*)(g_Y + (size_t)r0 * HID + col) = make_float2(D2[nc][0], D2[nc][1]);
        if (r1 < NN) *(float2*)(g_Y + (size_t)r1 * HID + col) = make_float2(D2[nc][2], D2[nc][3]);
    }
}

// ================================================================ k_final via mma.sync
__global__ __launch_bounds__(256, 2) void k_final_mma(
    const float* __restrict__ W2b, const float* __restrict__ bb,
    const float* __restrict__ ga,  const float* __restrict__ be,
    const float* __restrict__ mm,  const float* __restrict__ vv,
    const int* __restrict__ batch, float* __restrict__ out)
{
    extern __shared__ char smc[];
    uint32_t sb = smem_u32(smc);
    float* scp = (float*)(smc + FN_SC);
    float* shp = (float*)(smc + FN_SH);
    int tid = threadIdx.x;
    int w = tid >> 5, l = tid & 31;
    int m0 = blockIdx.x * 128;

    {
        int row = tid >> 1, half = tid & 1;
        int gm = m0 + row;
        bool ok = gm < NN;
        const float4* ar = (const float4*)(g_A + (size_t)gm * HID + half * 32);
        int rbase = row * RST2 + half * 64;
#pragma unroll
        for (int c = 0; c < 4; c++) {
            float4 f0 = ok ? ar[2 * c] : make_float4(0.f, 0.f, 0.f, 0.f);
            float4 f1 = ok ? ar[2 * c + 1] : make_float4(0.f, 0.f, 0.f, 0.f);
            float fv[8] = {fmaxf(f0.x, 0.f), fmaxf(f0.y, 0.f), fmaxf(f0.z, 0.f), fmaxf(f0.w, 0.f),
                           fmaxf(f1.x, 0.f), fmaxf(f1.y, 0.f), fmaxf(f1.z, 0.f), fmaxf(f1.w, 0.f)};
            uint32_t hp[4], lp[4];
            split8(fv, hp, lp);
            *(uint4*)(smc + FN_AH + rbase + c * 16) = make_uint4(hp[0], hp[1], hp[2], hp[3]);
            *(uint4*)(smc + FN_AL + rbase + c * 16) = make_uint4(lp[0], lp[1], lp[2], lp[3]);
        }
    }
    {
        int row = tid >> 2, q = tid & 3;
        const float4* wr = (const float4*)(W2b + (size_t)row * HID + q * 16);
#pragma unroll
        for (int c = 0; c < 2; c++) {
            int rb = row * RST2 + q * 32 + c * 16;
            float4 f0 = wr[2 * c], f1 = wr[2 * c + 1];
            float fv[8] = {f0.x, f0.y, f0.z, f0.w, f1.x, f1.y, f1.z, f1.w};
            uint32_t hp[4], lp[4];
            split8(fv, hp, lp);
            *(uint4*)(smc + FN_WH + rb) = make_uint4(hp[0], hp[1], hp[2], hp[3]);
            *(uint4*)(smc + FN_WL + rb) = make_uint4(lp[0], lp[1], lp[2], lp[3]);
        }
    }
    if (tid < HID) {
        float s = ga[tid] * rsqrtf(vv[tid] + BN_EPS_F);
        scp[tid] = s;
        shp[tid] = (bb[tid] - mm[tid]) * s + be[tid];
    }
    __syncthreads();

    uint32_t aAddr = sb + (uint32_t)((16 * w + (l & 15)) * RST2 + (l >> 4) * 16);
    int bN = (l & 7) + ((l >> 4) << 3);
    int bKc = (l >> 3) & 1;
    uint32_t bAddr = sb + (uint32_t)(bN * RST2 + bKc * 16);

    float D[8][4];
#pragma unroll
    for (int nc = 0; nc < 8; nc++)
#pragma unroll
        for (int j = 0; j < 4; j++) D[nc][j] = 0.f;

#pragma unroll
    for (int ks = 0; ks < 4; ks++) {
        uint32_t ko = ks * 32;
        uint32_t ah0, ah1, ah2, ah3, al0, al1, al2, al3;
        LDMX4(ah0, ah1, ah2, ah3, aAddr + FN_AH + ko);
        LDMX4(al0, al1, al2, al3, aAddr + FN_AL + ko);
#pragma unroll
        for (int g = 0; g < 4; g++) {
            uint32_t gb = bAddr + (uint32_t)(g * 16 * RST2) + ko;
            uint32_t bh0, bh1, bh2, bh3, bl0, bl1, bl2, bl3;
            LDMX4(bh0, bh1, bh2, bh3, gb + FN_WH);
            LDMX4(bl0, bl1, bl2, bl3, gb + FN_WL);
            MMA16816(D[2 * g],     ah0, ah1, ah2, ah3, bh0, bh1);
            MMA16816(D[2 * g],     ah0, ah1, ah2, ah3, bl0, bl1);
            MMA16816(D[2 * g],     al0, al1, al2, al3, bh0, bh1);
            MMA16816(D[2 * g + 1], ah0, ah1, ah2, ah3, bh2, bh3);
            MMA16816(D[2 * g + 1], ah0, ah1, ah2, ah3, bl2, bl3);
            MMA16816(D[2 * g + 1], al0, al1, al2, al3, bh2, bh3);
        }
    }

    int r0 = m0 + 16 * w + (l >> 2);
    int r1 = r0 + 8;
    int gb0 = (r0 < NN) ? batch[r0] : 0;
    int gb1 = (r1 < NN) ? batch[r1] : 0;
    int t2 = (l & 3) * 2;
#pragma unroll
    for (int nc = 0; nc < 8; nc++) {
        int col = nc * 8 + t2;
        float s0 = scp[col], s1 = scp[col + 1];
        float t0 = shp[col], t1 = shp[col + 1];
        if (r0 < NN)
            red_add_v2(out + (size_t)gb0 * HID + col,
                       fmaxf(fmaf(D[nc][0], s0, t0), 0.f),
                       fmaxf(fmaf(D[nc][1], s1, t1), 0.f));
        if (r1 < NN)
            red_add_v2(out + (size_t)gb1 * HID + col,
                       fmaxf(fmaf(D[nc][2], s0, t0), 0.f),
                       fmaxf(fmaf(D[nc][3], s1, t1), 0.f));
    }
}

// ------------------------------------------------- divide by per-graph counts
__global__ void k_div(const int* __restrict__ batch, float* __restrict__ out)
{
    int g = blockIdx.x;
    __shared__ int cnt;
    if (threadIdx.x == 0) {
        int lo = 0, hi = NN;
        while (lo < hi) { int mid = (lo + hi) >> 1; if (batch[mid] < g) lo = mid + 1; else hi = mid; }
        int lo2 = lo, hi2 = NN;
        while (lo2 < hi2) { int mid = (lo2 + hi2) >> 1; if (batch[mid] < g + 1) lo2 = mid + 1; else hi2 = mid; }
        cnt = lo2 - lo;
    }
    __syncthreads();
    float c = (float)(cnt > 1 ? cnt : 1);
    out[(size_t)g * HID + threadIdx.x] /= c;
}

// ---------------------------------------------------------------- launch
extern "C" void kernel_launch(void* const* d_in, const int* in_sizes, int n_in,
                              void* d_out, int out_size)
{
    (void)in_sizes; (void)n_in; (void)out_size;
    const float* x    = (const float*)d_in[0];
    const int*   ei   = (const int*)d_in[1];
    const int*   batch= (const int*)d_in[2];
    const float* W1a  = (const float*)d_in[3];
    const float* b1a  = (const float*)d_in[4];
    const float* W1b  = (const float*)d_in[5];
    const float* b1b  = (const float*)d_in[6];
    const float* g1   = (const float*)d_in[7];
    const float* be1  = (const float*)d_in[8];
    const float* m1   = (const float*)d_in[9];
    const float* v1   = (const float*)d_in[10];
    const float* W2a  = (const float*)d_in[11];
    const float* b2a  = (const float*)d_in[12];
    const float* W2b  = (const float*)d_in[13];
    const float* b2b  = (const float*)d_in[14];
    const float* g2   = (const float*)d_in[15];
    const float* be2  = (const float*)d_in[16];
    const float* m2   = (const float*)d_in[17];
    const float* v2   = (const float*)d_in[18];
    float* out = (float*)d_out;

    // one-time stream/event creation (first call = uncaptured correctness run)
    static cudaStream_t s2 = nullptr;
    static cudaEvent_t ev0 = nullptr, evA = nullptr;
    if (!s2) {
        cudaStreamCreateWithFlags(&s2, cudaStreamNonBlocking);
        cudaEventCreateWithFlags(&ev0, cudaEventDisableTiming);
        cudaEventCreateWithFlags(&evA, cudaEventDisableTiming);
    }

    cudaFuncSetAttribute(k_in_proj_mma, cudaFuncAttributeMaxDynamicSharedMemorySize, MMA_SMEM);
    cudaFuncSetAttribute(k_mid_mma,     cudaFuncAttributeMaxDynamicSharedMemorySize, MD_SMEM);
    cudaFuncSetAttribute(k_final_mma,   cudaFuncAttributeMaxDynamicSharedMemorySize, FN_SMEM);

    int gemmBlocks = (NN + 127) / 128;             // 782
    int edgeBlocks = (EE + 255) / 256;             // 6250
    int aggBlocks  = (NN * 16 + 255) / 256;        // 6250

    // ---- fork: in_proj runs concurrently with the CSR build chain
    cudaEventRecord(ev0, 0);
    cudaStreamWaitEvent(s2, ev0, 0);
    k_in_proj_mma<<<gemmBlocks, 256, MMA_SMEM, s2>>>(x, W1a);
    cudaEventRecord(evA, s2);

    // ---- CSR build chain on main stream
    k_zero_all<<<(NN + 255) / 256, 256>>>(out);
    k_hist<<<edgeBlocks, 256>>>(ei);
    k_scan1<<<NCHUNK, SCAN_CHUNK>>>();
    k_scan3f<<<(NN + 255) / 256, 256>>>();
    k_reorder<<<edgeBlocks, 256>>>(ei);

    // ---- join: aggregation needs both g_Y (s2) and CSR (main)
    cudaStreamWaitEvent(0, evA, 0);

    // layer 1 + mid
    k_agg<<<aggBlocks, 256>>>(b1a);
    k_mid_mma<<<gemmBlocks, 256, MD_SMEM>>>(W1b, b1b, g1, be1, m1, v1, W2a);

    // layer 2
    k_agg<<<aggBlocks, 256>>>(b2a);
    k_final_mma<<<gemmBlocks, 256, FN_SMEM>>>(W2b, b2b, g2, be2, m2, v2, batch, out);
    k_div<<<NG, HID>>>(batch, out);
}

// round 13
// speedup vs baseline: 1.5610x; 1.0395x over previous
#include <cuda_runtime.h>
#include <cuda_bf16.h>
#include <cuda_fp16.h>
#include <cstdint>

#define NN 100000
#define EE 1600000
#define FIN 128
#define HID 64
#define NG 512
#define BN_EPS_F 1e-5f

#define SCAN_CHUNK 1024
#define NCHUNK ((NN + SCAN_CHUNK - 1) / SCAN_CHUNK)   // 98

// mma.sync in_proj tile: SMEM bf16 rows padded (K=128 -> 136 elems = 272B)
#define RSTRB 272
#define XH_OFF 0
#define XL_OFF 34816
#define WH_OFF 69632
#define WL_OFF 87040
#define MMA_SMEM 104448

// K=64 mma tiles (mid / final): bf16 rows padded to 72 elems = 144B
#define RST2 144
#define MD_AH 0
#define MD_AL 18432
#define MD_W1H 36864
#define MD_W1L 46080
#define MD_W2H 55296
#define MD_W2L 64512
#define MD_SC 73728
#define MD_SH 73984
#define MD_SMEM 74240
#define FN_AH 0
#define FN_AL 18432
#define FN_WH 36864
#define FN_WL 46080
#define FN_SC 55296
#define FN_SH 55552
#define FN_SMEM 55808

typedef unsigned long long ull;

// Scratch (allocation-free rule: __device__ globals).
__device__ __align__(16) __half g_Yh[(size_t)NN * HID];  // fp16 projected rows (gather source)
__device__ __align__(16) float g_A[(size_t)NN * HID];    // fp32 aggregate
__device__ int g_cnt[NN];
__device__ int g_scan[NN];
__device__ int g_bsum[NCHUNK];
__device__ int g_rowptr[NN + 1];
__device__ int g_cursor[NN];
__device__ int g_ss[EE];

__device__ __forceinline__ void red_add_v2(float* p, float a, float b) {
    asm volatile("red.global.add.v2.f32 [%0], {%1,%2};"
                 :: "l"(p), "f"(a), "f"(b) : "memory");
}

__device__ __forceinline__ uint32_t smem_u32(const void* p) {
    uint32_t a;
    asm("{ .reg .u64 t; cvta.to.shared.u64 t, %1; cvt.u32.u64 %0, t; }" : "=r"(a) : "l"(p));
    return a;
}
#define BF2(res, a, b) asm("cvt.rn.satfinite.bf16x2.f32 %0, %1, %2;" : "=r"(res) : "f"(b), "f"(a))

#define LDMX4(r0, r1, r2, r3, addr)                                             \
    asm volatile("ldmatrix.sync.aligned.m8n8.x4.shared.b16 {%0,%1,%2,%3}, [%4];" \
                 : "=r"(r0), "=r"(r1), "=r"(r2), "=r"(r3) : "r"(addr))

#define MMA16816(d, a0, a1, a2, a3, b0, b1)                                     \
    asm volatile("mma.sync.aligned.m16n8k16.row.col.f32.bf16.bf16.f32 "         \
                 "{%0,%1,%2,%3}, {%4,%5,%6,%7}, {%8,%9}, {%0,%1,%2,%3};"        \
                 : "+f"((d)[0]), "+f"((d)[1]), "+f"((d)[2]), "+f"((d)[3])       \
                 : "r"(a0), "r"(a1), "r"(a2), "r"(a3), "r"(b0), "r"(b1))

__device__ __forceinline__ void split8(const float* fv, uint32_t* hp, uint32_t* lp) {
#pragma unroll
    for (int j = 0; j < 4; j++) {
        BF2(hp[j], fv[2 * j], fv[2 * j + 1]);
        float l0 = fv[2 * j]     - __uint_as_float(hp[j] << 16);
        float l1 = fv[2 * j + 1] - __uint_as_float(hp[j] & 0xFFFF0000u);
        BF2(lp[j], l0, l1);
    }
}

// convert uint4 (8 fp16) and accumulate into acc[8]
__device__ __forceinline__ void acc8h(uint4 h, float* acc) {
    float2 p;
    p = __half22float2(*(__half2*)&h.x); acc[0] += p.x; acc[1] += p.y;
    p = __half22float2(*(__half2*)&h.y); acc[2] += p.x; acc[3] += p.y;
    p = __half22float2(*(__half2*)&h.z); acc[4] += p.x; acc[5] += p.y;
    p = __half22float2(*(__half2*)&h.w); acc[6] += p.x; acc[7] += p.y;
}

// ---------------------------------------------------------------- fused zero
__global__ void k_zero_all(float* __restrict__ out) {
    int i = blockIdx.x * blockDim.x + threadIdx.x;
    if (i < NG * HID) out[i] = 0.f;
    if (i < NN) g_cnt[i] = 0;
}

// ---------------------------------------------------------------- CSR build
__global__ void k_hist(const int* __restrict__ ei) {
    int e = blockIdx.x * blockDim.x + threadIdx.x;
    if (e < EE) atomicAdd(&g_cnt[ei[EE + e]], 1);
}

__global__ __launch_bounds__(SCAN_CHUNK) void k_scan1() {
    __shared__ int s[SCAN_CHUNK];
    int tid = threadIdx.x;
    int i = blockIdx.x * SCAN_CHUNK + tid;
    int v = (i < NN) ? g_cnt[i] : 0;
    s[tid] = v;
    __syncthreads();
#pragma unroll
    for (int off = 1; off < SCAN_CHUNK; off <<= 1) {
        int t = (tid >= off) ? s[tid - off] : 0;
        __syncthreads();
        s[tid] += t;
        __syncthreads();
    }
    if (i < NN) g_scan[i] = s[tid];
    if (tid == SCAN_CHUNK - 1) g_bsum[blockIdx.x] = s[tid];
}

__global__ void k_scan3f() {
    __shared__ int boff[NCHUNK];
    if (threadIdx.x == 0) {
        int run = 0;
#pragma unroll 2
        for (int c = 0; c < NCHUNK; c++) { int t = g_bsum[c]; boff[c] = run; run += t; }
    }
    __syncthreads();
    int i = blockIdx.x * blockDim.x + threadIdx.x;
    if (i >= NN) return;
    int incl = g_scan[i] + boff[i / SCAN_CHUNK];
    g_rowptr[i + 1] = incl;
    g_cursor[i] = incl - g_cnt[i];
    if (i == 0) g_rowptr[0] = 0;
}

__global__ void k_reorder(const int* __restrict__ ei) {
    int e = blockIdx.x * blockDim.x + threadIdx.x;
    if (e >= EE) return;
    int d = ei[EE + e];
    int pos = atomicAdd(&g_cursor[d], 1);
    g_ss[pos] = ei[e];
}

// ---------------------------------------------------------------- aggregation (fp16 gather)
// A[n] = Yh[n] + bias + sum_nbr Yh[s]; 8 threads/node, uint4 (8 fp16) per thread.
__global__ __launch_bounds__(256) void k_agg(const float* __restrict__ b) {
    int t = blockIdx.x * 256 + threadIdx.x;
    int n = t >> 3;
    int lane = t & 7;
    if (n >= NN) return;

    const uint4* Yh4 = (const uint4*)g_Yh;   // 8 uint4 per row
    float acc[8];
    {
        float4 b0 = ((const float4*)b)[2 * lane];
        float4 b1 = ((const float4*)b)[2 * lane + 1];
        acc[0] = b0.x; acc[1] = b0.y; acc[2] = b0.z; acc[3] = b0.w;
        acc[4] = b1.x; acc[5] = b1.y; acc[6] = b1.z; acc[7] = b1.w;
    }
    acc8h(Yh4[(size_t)n * 8 + lane], acc);   // self

    int beg = g_rowptr[n], end = g_rowptr[n + 1];
#pragma unroll 4
    for (int e = beg; e < end; e++) {
        int s = g_ss[e];
        acc8h(Yh4[(size_t)s * 8 + lane], acc);
    }
    float4* A4 = (float4*)g_A + (size_t)n * 16 + 2 * lane;
    A4[0] = make_float4(acc[0], acc[1], acc[2], acc[3]);
    A4[1] = make_float4(acc[4], acc[5], acc[6], acc[7]);
}

// ================================================================ in_proj via mma.sync
__global__ __launch_bounds__(256, 2) void k_in_proj_mma(
    const float* __restrict__ x, const float* __restrict__ W)
{
    extern __shared__ char smc[];
    uint32_t sb = smem_u32(smc);
    int tid = threadIdx.x;
    int w = tid >> 5, l = tid & 31;
    int m0 = blockIdx.x * 128;

    {
        int row = tid >> 1, half = tid & 1;
        int gm = m0 + row;
        bool ok = gm < NN;
        const float4* xr = (const float4*)(x + (size_t)gm * FIN + half * 64);
        int rbase = row * RSTRB + half * 128;
#pragma unroll
        for (int c = 0; c < 8; c++) {
            float4 f0 = ok ? xr[2 * c] : make_float4(0.f, 0.f, 0.f, 0.f);
            float4 f1 = ok ? xr[2 * c + 1] : make_float4(0.f, 0.f, 0.f, 0.f);
            float fv[8] = {f0.x, f0.y, f0.z, f0.w, f1.x, f1.y, f1.z, f1.w};
            uint32_t hp[4], lp[4];
            split8(fv, hp, lp);
            *(uint4*)(smc + XH_OFF + rbase + c * 16) = make_uint4(hp[0], hp[1], hp[2], hp[3]);
            *(uint4*)(smc + XL_OFF + rbase + c * 16) = make_uint4(lp[0], lp[1], lp[2], lp[3]);
        }
    }
    {
        int row = tid >> 2, q = tid & 3;
        const float4* wr = (const float4*)(W + (size_t)row * FIN + q * 32);
        int rbase = row * RSTRB + q * 64;
#pragma unroll
        for (int c = 0; c < 4; c++) {
            float4 f0 = wr[2 * c];
            float4 f1 = wr[2 * c + 1];
            float fv[8] = {f0.x, f0.y, f0.z, f0.w, f1.x, f1.y, f1.z, f1.w};
            uint32_t hp[4], lp[4];
            split8(fv, hp, lp);
            *(uint4*)(smc + WH_OFF + rbase + c * 16) = make_uint4(hp[0], hp[1], hp[2], hp[3]);
            *(uint4*)(smc + WL_OFF + rbase + c * 16) = make_uint4(lp[0], lp[1], lp[2], lp[3]);
        }
    }
    __syncthreads();

    uint32_t aAddr = sb + (uint32_t)((16 * w + (l & 15)) * RSTRB + (l >> 4) * 16);
    int bN = (l & 7) + ((l >> 4) << 3);
    int bKc = (l >> 3) & 1;
    uint32_t bAddr = sb + (uint32_t)(bN * RSTRB + bKc * 16);

    float D[8][4];
#pragma unroll
    for (int nc = 0; nc < 8; nc++)
#pragma unroll
        for (int j = 0; j < 4; j++) D[nc][j] = 0.f;

#pragma unroll
    for (int ks = 0; ks < 8; ks++) {
        uint32_t ko = ks * 32;
        uint32_t ah0, ah1, ah2, ah3, al0, al1, al2, al3;
        LDMX4(ah0, ah1, ah2, ah3, aAddr + XH_OFF + ko);
        LDMX4(al0, al1, al2, al3, aAddr + XL_OFF + ko);
#pragma unroll
        for (int g = 0; g < 4; g++) {
            uint32_t gb = bAddr + (uint32_t)(g * 16 * RSTRB) + ko;
            uint32_t bh0, bh1, bh2, bh3, bl0, bl1, bl2, bl3;
            LDMX4(bh0, bh1, bh2, bh3, gb + WH_OFF);
            LDMX4(bl0, bl1, bl2, bl3, gb + WL_OFF);
            MMA16816(D[2 * g],     ah0, ah1, ah2, ah3, bh0, bh1);
            MMA16816(D[2 * g],     ah0, ah1, ah2, ah3, bl0, bl1);
            MMA16816(D[2 * g],     al0, al1, al2, al3, bh0, bh1);
            MMA16816(D[2 * g + 1], ah0, ah1, ah2, ah3, bh2, bh3);
            MMA16816(D[2 * g + 1], ah0, ah1, ah2, ah3, bl2, bl3);
            MMA16816(D[2 * g + 1], al0, al1, al2, al3, bh2, bh3);
        }
    }

    int r0 = m0 + 16 * w + (l >> 2);
    int r1 = r0 + 8;
#pragma unroll
    for (int nc = 0; nc < 8; nc++) {
        int col = nc * 8 + (l & 3) * 2;
        if (r0 < NN) *(__half2*)(g_Yh + (size_t)r0 * HID + col) = __floats2half2_rn(D[nc][0], D[nc][1]);
        if (r1 < NN) *(__half2*)(g_Yh + (size_t)r1 * HID + col) = __floats2half2_rn(D[nc][2], D[nc][3]);
    }
}

// ================================================================ k_mid via mma.sync
__global__ __launch_bounds__(256, 2) void k_mid_mma(
    const float* __restrict__ W1b, const float* __restrict__ b1b,
    const float* __restrict__ g1,  const float* __restrict__ be1,
    const float* __restrict__ m1,  const float* __restrict__ v1,
    const float* __restrict__ W2a)
{
    extern __shared__ char smc[];
    uint32_t sb = smem_u32(smc);
    float* scp = (float*)(smc + MD_SC);
    float* shp = (float*)(smc + MD_SH);
    int tid = threadIdx.x;
    int w = tid >> 5, l = tid & 31;
    int m0 = blockIdx.x * 128;

    {
        int row = tid >> 1, half = tid & 1;
        int gm = m0 + row;
        bool ok = gm < NN;
        const float4* ar = (const float4*)(g_A + (size_t)gm * HID + half * 32);
        int rbase = row * RST2 + half * 64;
#pragma unroll
        for (int c = 0; c < 4; c++) {
            float4 f0 = ok ? ar[2 * c] : make_float4(0.f, 0.f, 0.f, 0.f);
            float4 f1 = ok ? ar[2 * c + 1] : make_float4(0.f, 0.f, 0.f, 0.f);
            float fv[8] = {fmaxf(f0.x, 0.f), fmaxf(f0.y, 0.f), fmaxf(f0.z, 0.f), fmaxf(f0.w, 0.f),
                           fmaxf(f1.x, 0.f), fmaxf(f1.y, 0.f), fmaxf(f1.z, 0.f), fmaxf(f1.w, 0.f)};
            uint32_t hp[4], lp[4];
            split8(fv, hp, lp);
            *(uint4*)(smc + MD_AH + rbase + c * 16) = make_uint4(hp[0], hp[1], hp[2], hp[3]);
            *(uint4*)(smc + MD_AL + rbase + c * 16) = make_uint4(lp[0], lp[1], lp[2], lp[3]);
        }
    }
    {
        int row = tid >> 2, q = tid & 3;
        const float4* w1r = (const float4*)(W1b + (size_t)row * HID + q * 16);
        const float4* w2r = (const float4*)(W2a + (size_t)row * HID + q * 16);
#pragma unroll
        for (int c = 0; c < 2; c++) {
            int rb = row * RST2 + q * 32 + c * 16;
            float4 f0 = w1r[2 * c], f1 = w1r[2 * c + 1];
            float fv[8] = {f0.x, f0.y, f0.z, f0.w, f1.x, f1.y, f1.z, f1.w};
            uint32_t hp[4], lp[4];
            split8(fv, hp, lp);
            *(uint4*)(smc + MD_W1H + rb) = make_uint4(hp[0], hp[1], hp[2], hp[3]);
            *(uint4*)(smc + MD_W1L + rb) = make_uint4(lp[0], lp[1], lp[2], lp[3]);
            f0 = w2r[2 * c]; f1 = w2r[2 * c + 1];
            float gv[8] = {f0.x, f0.y, f0.z, f0.w, f1.x, f1.y, f1.z, f1.w};
            split8(gv, hp, lp);
            *(uint4*)(smc + MD_W2H + rb) = make_uint4(hp[0], hp[1], hp[2], hp[3]);
            *(uint4*)(smc + MD_W2L + rb) = make_uint4(lp[0], lp[1], lp[2], lp[3]);
        }
    }
    if (tid < HID) {
        float s = g1[tid] * rsqrtf(v1[tid] + BN_EPS_F);
        scp[tid] = s;
        shp[tid] = (b1b[tid] - m1[tid]) * s + be1[tid];
    }
    __syncthreads();

    uint32_t aAddr = sb + (uint32_t)((16 * w + (l & 15)) * RST2 + (l >> 4) * 16);
    int bN = (l & 7) + ((l >> 4) << 3);
    int bKc = (l >> 3) & 1;
    uint32_t bAddr = sb + (uint32_t)(bN * RST2 + bKc * 16);

    float D[8][4];
#pragma unroll
    for (int nc = 0; nc < 8; nc++)
#pragma unroll
        for (int j = 0; j < 4; j++) D[nc][j] = 0.f;

#pragma unroll
    for (int ks = 0; ks < 4; ks++) {
        uint32_t ko = ks * 32;
        uint32_t ah0, ah1, ah2, ah3, al0, al1, al2, al3;
        LDMX4(ah0, ah1, ah2, ah3, aAddr + MD_AH + ko);
        LDMX4(al0, al1, al2, al3, aAddr + MD_AL + ko);
#pragma unroll
        for (int g = 0; g < 4; g++) {
            uint32_t gb = bAddr + (uint32_t)(g * 16 * RST2) + ko;
            uint32_t bh0, bh1, bh2, bh3, bl0, bl1, bl2, bl3;
            LDMX4(bh0, bh1, bh2, bh3, gb + MD_W1H);
            LDMX4(bl0, bl1, bl2, bl3, gb + MD_W1L);
            MMA16816(D[2 * g],     ah0, ah1, ah2, ah3, bh0, bh1);
            MMA16816(D[2 * g],     ah0, ah1, ah2, ah3, bl0, bl1);
            MMA16816(D[2 * g],     al0, al1, al2, al3, bh0, bh1);
            MMA16816(D[2 * g + 1], ah0, ah1, ah2, ah3, bh2, bh3);
            MMA16816(D[2 * g + 1], ah0, ah1, ah2, ah3, bl2, bl3);
            MMA16816(D[2 * g + 1], al0, al1, al2, al3, bh2, bh3);
        }
    }

    uint32_t ahi[4][4], alo[4][4];
    {
        int t2 = (l & 3) * 2;
#pragma unroll
        for (int nc = 0; nc < 8; nc++) {
            int col = nc * 8 + t2;
            float s0 = scp[col], s1 = scp[col + 1];
            float t0 = shp[col], t1 = shp[col + 1];
            D[nc][0] = fmaxf(fmaf(D[nc][0], s0, t0), 0.f);
            D[nc][1] = fmaxf(fmaf(D[nc][1], s1, t1), 0.f);
            D[nc][2] = fmaxf(fmaf(D[nc][2], s0, t0), 0.f);
            D[nc][3] = fmaxf(fmaf(D[nc][3], s1, t1), 0.f);
        }
#pragma unroll
        for (int kc = 0; kc < 4; kc++) {
#pragma unroll
            for (int j = 0; j < 4; j++) {
                float h0 = D[2 * kc + (j >> 1)][(j & 1) * 2 + 0];
                float h1 = D[2 * kc + (j >> 1)][(j & 1) * 2 + 1];
                uint32_t hp;
                BF2(hp, h0, h1);
                float l0 = h0 - __uint_as_float(hp << 16);
                float l1 = h1 - __uint_as_float(hp & 0xFFFF0000u);
                uint32_t lp;
                BF2(lp, l0, l1);
                ahi[kc][j] = hp;
                alo[kc][j] = lp;
            }
        }
    }

    float D2[8][4];
#pragma unroll
    for (int nc = 0; nc < 8; nc++)
#pragma unroll
        for (int j = 0; j < 4; j++) D2[nc][j] = 0.f;

#pragma unroll
    for (int kc = 0; kc < 4; kc++) {
        uint32_t ko = kc * 32;
#pragma unroll
        for (int g = 0; g < 4; g++) {
            uint32_t gb = bAddr + (uint32_t)(g * 16 * RST2) + ko;
            uint32_t bh0, bh1, bh2, bh3, bl0, bl1, bl2, bl3;
            LDMX4(bh0, bh1, bh2, bh3, gb + MD_W2H);
            LDMX4(bl0, bl1, bl2, bl3, gb + MD_W2L);
            MMA16816(D2[2 * g],     ahi[kc][0], ahi[kc][1], ahi[kc][2], ahi[kc][3], bh0, bh1);
            MMA16816(D2[2 * g],     ahi[kc][0], ahi[kc][1], ahi[kc][2], ahi[kc][3], bl0, bl1);
            MMA16816(D2[2 * g],     alo[kc][0], alo[kc][1], alo[kc][2], alo[kc][3], bh0, bh1);
            MMA16816(D2[2 * g + 1], ahi[kc][0], ahi[kc][1], ahi[kc][2], ahi[kc][3], bh2, bh3);
            MMA16816(D2[2 * g + 1], ahi[kc][0], ahi[kc][1], ahi[kc][2], ahi[kc][3], bl2, bl3);
            MMA16816(D2[2 * g + 1], alo[kc][0], alo[kc][1], alo[kc][2], alo[kc][3], bh2, bh3);
        }
    }

    int r0 = m0 + 16 * w + (l >> 2);
    int r1 = r0 + 8;
#pragma unroll
    for (int nc = 0; nc < 8; nc++) {
        int col = nc * 8 + (l & 3) * 2;
        if (r0 < NN) *(__half2*)(g_Yh + (size_t)r0 * HID + col) = __floats2half2_rn(D2[nc][0], D2[nc][1]);
        if (r1 < NN) *(__half2*)(g_Yh + (size_t)r1 * HID + col) = __floats2half2_rn(D2[nc][2], D2[nc][3]);
    }
}

// ================================================================ k_final via mma.sync
__global__ __launch_bounds__(256, 2) void k_final_mma(
    const float* __restrict__ W2b, const float* __restrict__ bb,
    const float* __restrict__ ga,  const float* __restrict__ be,
    const float* __restrict__ mm,  const float* __restrict__ vv,
    const int* __restrict__ batch, float* __restrict__ out)
{
    extern __shared__ char smc[];
    uint32_t sb = smem_u32(smc);
    float* scp = (float*)(smc + FN_SC);
    float* shp = (float*)(smc + FN_SH);
    int tid = threadIdx.x;
    int w = tid >> 5, l = tid & 31;
    int m0 = blockIdx.x * 128;

    {
        int row = tid >> 1, half = tid & 1;
        int gm = m0 + row;
        bool ok = gm < NN;
        const float4* ar = (const float4*)(g_A + (size_t)gm * HID + half * 32);
        int rbase = row * RST2 + half * 64;
#pragma unroll
        for (int c = 0; c < 4; c++) {
            float4 f0 = ok ? ar[2 * c] : make_float4(0.f, 0.f, 0.f, 0.f);
            float4 f1 = ok ? ar[2 * c + 1] : make_float4(0.f, 0.f, 0.f, 0.f);
            float fv[8] = {fmaxf(f0.x, 0.f), fmaxf(f0.y, 0.f), fmaxf(f0.z, 0.f), fmaxf(f0.w, 0.f),
                           fmaxf(f1.x, 0.f), fmaxf(f1.y, 0.f), fmaxf(f1.z, 0.f), fmaxf(f1.w, 0.f)};
            uint32_t hp[4], lp[4];
            split8(fv, hp, lp);
            *(uint4*)(smc + FN_AH + rbase + c * 16) = make_uint4(hp[0], hp[1], hp[2], hp[3]);
            *(uint4*)(smc + FN_AL + rbase + c * 16) = make_uint4(lp[0], lp[1], lp[2], lp[3]);
        }
    }
    {
        int row = tid >> 2, q = tid & 3;
        const float4* wr = (const float4*)(W2b + (size_t)row * HID + q * 16);
#pragma unroll
        for (int c = 0; c < 2; c++) {
            int rb = row * RST2 + q * 32 + c * 16;
            float4 f0 = wr[2 * c], f1 = wr[2 * c + 1];
            float fv[8] = {f0.x, f0.y, f0.z, f0.w, f1.x, f1.y, f1.z, f1.w};
            uint32_t hp[4], lp[4];
            split8(fv, hp, lp);
            *(uint4*)(smc + FN_WH + rb) = make_uint4(hp[0], hp[1], hp[2], hp[3]);
            *(uint4*)(smc + FN_WL + rb) = make_uint4(lp[0], lp[1], lp[2], lp[3]);
        }
    }
    if (tid < HID) {
        float s = ga[tid] * rsqrtf(vv[tid] + BN_EPS_F);
        scp[tid] = s;
        shp[tid] = (bb[tid] - mm[tid]) * s + be[tid];
    }
    __syncthreads();

    uint32_t aAddr = sb + (uint32_t)((16 * w + (l & 15)) * RST2 + (l >> 4) * 16);
    int bN = (l & 7) + ((l >> 4) << 3);
    int bKc = (l >> 3) & 1;
    uint32_t bAddr = sb + (uint32_t)(bN * RST2 + bKc * 16);

    float D[8][4];
#pragma unroll
    for (int nc = 0; nc < 8; nc++)
#pragma unroll
        for (int j = 0; j < 4; j++) D[nc][j] = 0.f;

#pragma unroll
    for (int ks = 0; ks < 4; ks++) {
        uint32_t ko = ks * 32;
        uint32_t ah0, ah1, ah2, ah3, al0, al1, al2, al3;
        LDMX4(ah0, ah1, ah2, ah3, aAddr + FN_AH + ko);
        LDMX4(al0, al1, al2, al3, aAddr + FN_AL + ko);
#pragma unroll
        for (int g = 0; g < 4; g++) {
            uint32_t gb = bAddr + (uint32_t)(g * 16 * RST2) + ko;
            uint32_t bh0, bh1, bh2, bh3, bl0, bl1, bl2, bl3;
            LDMX4(bh0, bh1, bh2, bh3, gb + FN_WH);
            LDMX4(bl0, bl1, bl2, bl3, gb + FN_WL);
            MMA16816(D[2 * g],     ah0, ah1, ah2, ah3, bh0, bh1);
            MMA16816(D[2 * g],     ah0, ah1, ah2, ah3, bl0, bl1);
            MMA16816(D[2 * g],     al0, al1, al2, al3, bh0, bh1);
            MMA16816(D[2 * g + 1], ah0, ah1, ah2, ah3, bh2, bh3);
            MMA16816(D[2 * g + 1], ah0, ah1, ah2, ah3, bl2, bl3);
            MMA16816(D[2 * g + 1], al0, al1, al2, al3, bh2, bh3);
        }
    }

    int r0 = m0 + 16 * w + (l >> 2);
    int r1 = r0 + 8;
    int gb0 = (r0 < NN) ? batch[r0] : 0;
    int gb1 = (r1 < NN) ? batch[r1] : 0;
    int t2 = (l & 3) * 2;
#pragma unroll
    for (int nc = 0; nc < 8; nc++) {
        int col = nc * 8 + t2;
        float s0 = scp[col], s1 = scp[col + 1];
        float t0 = shp[col], t1 = shp[col + 1];
        if (r0 < NN)
            red_add_v2(out + (size_t)gb0 * HID + col,
                       fmaxf(fmaf(D[nc][0], s0, t0), 0.f),
                       fmaxf(fmaf(D[nc][1], s1, t1), 0.f));
        if (r1 < NN)
            red_add_v2(out + (size_t)gb1 * HID + col,
                       fmaxf(fmaf(D[nc][2], s0, t0), 0.f),
                       fmaxf(fmaf(D[nc][3], s1, t1), 0.f));
    }
}

// ------------------------------------------------- divide by per-graph counts
__global__ void k_div(const int* __restrict__ batch, float* __restrict__ out)
{
    int g = blockIdx.x;
    __shared__ int cnt;
    if (threadIdx.x == 0) {
        int lo = 0, hi = NN;
        while (lo < hi) { int mid = (lo + hi) >> 1; if (batch[mid] < g) lo = mid + 1; else hi = mid; }
        int lo2 = lo, hi2 = NN;
        while (lo2 < hi2) { int mid = (lo2 + hi2) >> 1; if (batch[mid] < g + 1) lo2 = mid + 1; else hi2 = mid; }
        cnt = lo2 - lo;
    }
    __syncthreads();
    float c = (float)(cnt > 1 ? cnt : 1);
    out[(size_t)g * HID + threadIdx.x] /= c;
}

// ---------------------------------------------------------------- launch
extern "C" void kernel_launch(void* const* d_in, const int* in_sizes, int n_in,
                              void* d_out, int out_size)
{
    (void)in_sizes; (void)n_in; (void)out_size;
    const float* x    = (const float*)d_in[0];
    const int*   ei   = (const int*)d_in[1];
    const int*   batch= (const int*)d_in[2];
    const float* W1a  = (const float*)d_in[3];
    const float* b1a  = (const float*)d_in[4];
    const float* W1b  = (const float*)d_in[5];
    const float* b1b  = (const float*)d_in[6];
    const float* g1   = (const float*)d_in[7];
    const float* be1  = (const float*)d_in[8];
    const float* m1   = (const float*)d_in[9];
    const float* v1   = (const float*)d_in[10];
    const float* W2a  = (const float*)d_in[11];
    const float* b2a  = (const float*)d_in[12];
    const float* W2b  = (const float*)d_in[13];
    const float* b2b  = (const float*)d_in[14];
    const float* g2   = (const float*)d_in[15];
    const float* be2  = (const float*)d_in[16];
    const float* m2   = (const float*)d_in[17];
    const float* v2   = (const float*)d_in[18];
    float* out = (float*)d_out;

    static cudaStream_t s2 = nullptr;
    static cudaEvent_t ev0 = nullptr, evA = nullptr;
    if (!s2) {
        cudaStreamCreateWithFlags(&s2, cudaStreamNonBlocking);
        cudaEventCreateWithFlags(&ev0, cudaEventDisableTiming);
        cudaEventCreateWithFlags(&evA, cudaEventDisableTiming);
    }

    cudaFuncSetAttribute(k_in_proj_mma, cudaFuncAttributeMaxDynamicSharedMemorySize, MMA_SMEM);
    cudaFuncSetAttribute(k_mid_mma,     cudaFuncAttributeMaxDynamicSharedMemorySize, MD_SMEM);
    cudaFuncSetAttribute(k_final_mma,   cudaFuncAttributeMaxDynamicSharedMemorySize, FN_SMEM);

    int gemmBlocks = (NN + 127) / 128;             // 782
    int edgeBlocks = (EE + 255) / 256;             // 6250
    int aggBlocks  = (NN * 8 + 255) / 256;         // 3125

    // fork: in_proj concurrent with CSR build
    cudaEventRecord(ev0, 0);
    cudaStreamWaitEvent(s2, ev0, 0);
    k_in_proj_mma<<<gemmBlocks, 256, MMA_SMEM, s2>>>(x, W1a);
    cudaEventRecord(evA, s2);

    k_zero_all<<<(NN + 255) / 256, 256>>>(out);
    k_hist<<<edgeBlocks, 256>>>(ei);
    k_scan1<<<NCHUNK, SCAN_CHUNK>>>();
    k_scan3f<<<(NN + 255) / 256, 256>>>();
    k_reorder<<<edgeBlocks, 256>>>(ei);

    cudaStreamWaitEvent(0, evA, 0);

    // layer 1 + mid
    k_agg<<<aggBlocks, 256>>>(b1a);
    k_mid_mma<<<gemmBlocks, 256, MD_SMEM>>>(W1b, b1b, g1, be1, m1, v1, W2a);

    // layer 2
    k_agg<<<aggBlocks, 256>>>(b2a);
    k_final_mma<<<gemmBlocks, 256, FN_SMEM>>>(W2b, b2b, g2, be2, m2, v2, batch, out);
    k_div<<<NG, HID>>>(batch, out);
}